// round 8
// baseline (speedup 1.0000x reference)
#include <cuda_runtime.h>
#include <cuda_bf16.h>
#include <cstdint>
#include <math.h>

// Problem constants
#define NROWS 32768        // B*L = 8*4096
#define DD    1024
#define NGC   1024
#define NLC   256
#define NCC   1280
#define MOM_G 0.999f
#define MOM_L 0.8f
#define TEMP_INV (1.0f/0.07f)
#define EPSN  1e-12f

// ================= scratch (device globals) =================
// fp32: g_hidden: relu -> znorm -> gate ; g_unorm: unorm -> wu
__device__ float g_hidden[NROWS * DD];
__device__ float g_zproj [NROWS * DD];
__device__ float g_unorm [NROWS * DD];
__device__ float g_S     [NROWS * NCC];
__device__ float g_comb  [NCC * DD];
__device__ float g_sums  [NCC * DD];
__device__ float g_counts[NCC];
__device__ int   g_idx   [2 * NROWS];
__device__ double g_loss [3];
// bf16 hi/lo staging (sequentially reused for every GEMM operand)
__device__ __nv_bfloat16 g_Ah[(size_t)NROWS * NCC];
__device__ __nv_bfloat16 g_Al[(size_t)NROWS * NCC];
__device__ __nv_bfloat16 g_Bh[(size_t)NCC * DD];
__device__ __nv_bfloat16 g_Bl[(size_t)NCC * DD];

// ================= mma / ldmatrix / cp.async helpers =================
__device__ __forceinline__ void ldsm4(uint32_t r[4], uint32_t addr) {
    asm volatile("ldmatrix.sync.aligned.m8n8.x4.shared.b16 {%0,%1,%2,%3}, [%4];"
        : "=r"(r[0]), "=r"(r[1]), "=r"(r[2]), "=r"(r[3]) : "r"(addr));
}
__device__ __forceinline__ void mma_bf16(float c[4], const uint32_t a[4], const uint32_t b[2]) {
    asm volatile("mma.sync.aligned.m16n8k16.row.col.f32.bf16.bf16.f32 "
        "{%0,%1,%2,%3}, {%4,%5,%6,%7}, {%8,%9}, {%0,%1,%2,%3};"
        : "+f"(c[0]), "+f"(c[1]), "+f"(c[2]), "+f"(c[3])
        : "r"(a[0]), "r"(a[1]), "r"(a[2]), "r"(a[3]), "r"(b[0]), "r"(b[1]));
}
#define CP16(dst_u32, src_ptr) \
    asm volatile("cp.async.cg.shared.global [%0], [%1], 16;" :: "r"(dst_u32), "l"(src_ptr))
#define CP_COMMIT() asm volatile("cp.async.commit_group;" ::: "memory")
#define CP_WAIT1()  asm volatile("cp.async.wait_group 1;" ::: "memory")
#define CP_WAIT0()  asm volatile("cp.async.wait_group 0;" ::: "memory")

#define BPITCH 80            // bytes per SMEM row: 32 bf16 (64B) + 16B pad -> conflict-free LDSM
#define TILEB  (128 * BPITCH)  // 10240 B per tile part

// ============ bf16x3 GEMM: C[M,N] = A[M,K] @ B[N,K]^T ============
// CTA 128x128, warp 64x32, BK=32 (2 k16 steps). ACT: 0 none, 1 relu, 2 sigmoid.
// C2 (optional): scalar-store duplicate of C (possibly unaligned base).
template<int ACT>
__global__ __launch_bounds__(256, 2) void bgemm(
    const __nv_bfloat16* __restrict__ Ah, const __nv_bfloat16* __restrict__ Al,
    const __nv_bfloat16* __restrict__ Bh, const __nv_bfloat16* __restrict__ Bl,
    const float* __restrict__ bias, float* __restrict__ C,
    float* __restrict__ C2, int N, int K, int ldc)
{
    extern __shared__ char sm[];
    const int tid = threadIdx.x, lane = tid & 31, wid = tid >> 5;
    const int wm = wid >> 2, wn = wid & 3;
    const int m0 = blockIdx.y * 128, n0 = blockIdx.x * 128;
    const uint32_t sbase = (uint32_t)__cvta_generic_to_shared(sm);
    const int NK = K / 32;

    // loader: each thread covers 16 elems (32B) of one row per tile part
    const int lr = tid >> 1;
    const int lco = (tid & 1) * 16;  // element offset
    const __nv_bfloat16* pAh = Ah + (size_t)(m0 + lr) * K + lco;
    const __nv_bfloat16* pAl = Al + (size_t)(m0 + lr) * K + lco;
    const __nv_bfloat16* pBh = Bh + (size_t)(n0 + lr) * K + lco;
    const __nv_bfloat16* pBl = Bl + (size_t)(n0 + lr) * K + lco;
    const uint32_t dbase = sbase + lr * BPITCH + (tid & 1) * 32;

    #define LOADT(kt, buf) do { \
        int ko = (kt) * 32; \
        uint32_t d = dbase + (buf) * 4 * TILEB; \
        CP16(d,                 pAh + ko); CP16(d + 16,             pAh + ko + 8); \
        CP16(d + TILEB,         pAl + ko); CP16(d + TILEB + 16,     pAl + ko + 8); \
        CP16(d + 2 * TILEB,     pBh + ko); CP16(d + 2 * TILEB + 16, pBh + ko + 8); \
        CP16(d + 3 * TILEB,     pBl + ko); CP16(d + 3 * TILEB + 16, pBl + ko + 8); \
    } while (0)

    float acc[4][4][4];
    #pragma unroll
    for (int i = 0; i < 4; i++)
        #pragma unroll
        for (int j = 0; j < 4; j++)
            #pragma unroll
            for (int q = 0; q < 4; q++) acc[i][j][q] = 0.0f;

    LOADT(0, 0);
    CP_COMMIT();

    const int g = lane >> 3, l7 = lane & 7;
    for (int kt = 0; kt < NK; kt++) {
        const int buf = kt & 1;
        if (kt + 1 < NK) { LOADT(kt + 1, buf ^ 1); CP_COMMIT(); CP_WAIT1(); }
        else             { CP_WAIT0(); }
        __syncthreads();

        const uint32_t sA  = sbase + buf * 4 * TILEB;
        const uint32_t sAl = sA + TILEB;
        const uint32_t sB  = sA + 2 * TILEB;
        const uint32_t sBl = sA + 3 * TILEB;

        #pragma unroll
        for (int ks = 0; ks < 2; ks++) {
            uint32_t bh[4][2], bl[4][2];
            #pragma unroll
            for (int nj = 0; nj < 2; nj++) {
                // x4: lanes 0-7 -> (nblk0,k0), 8-15 -> (nblk0,k1), 16-23 -> (nblk1,k0), 24-31 -> (nblk1,k1)
                uint32_t nrow = wn * 32 + nj * 16 + (g >> 1) * 8 + l7;
                uint32_t kb = ks * 32 + (g & 1) * 16;
                uint32_t r[4];
                ldsm4(r, sB + nrow * BPITCH + kb);
                bh[nj * 2 + 0][0] = r[0]; bh[nj * 2 + 0][1] = r[1];
                bh[nj * 2 + 1][0] = r[2]; bh[nj * 2 + 1][1] = r[3];
                ldsm4(r, sBl + nrow * BPITCH + kb);
                bl[nj * 2 + 0][0] = r[0]; bl[nj * 2 + 0][1] = r[1];
                bl[nj * 2 + 1][0] = r[2]; bl[nj * 2 + 1][1] = r[3];
            }
            #pragma unroll
            for (int mi = 0; mi < 4; mi++) {
                // x4: lanes 0-7 -> (rows0-7,k0), 8-15 -> (rows8-15,k0), 16-23 -> (rows0-7,k1), 24-31 -> (rows8-15,k1)
                uint32_t arow = wm * 64 + mi * 16 + (g & 1) * 8 + l7;
                uint32_t kb = ks * 32 + (g >> 1) * 16;
                uint32_t ahf[4], alf[4];
                ldsm4(ahf, sA  + arow * BPITCH + kb);
                ldsm4(alf, sAl + arow * BPITCH + kb);
                #pragma unroll
                for (int ni = 0; ni < 4; ni++) {
                    mma_bf16(acc[mi][ni], ahf, bh[ni]);
                    mma_bf16(acc[mi][ni], ahf, bl[ni]);
                    mma_bf16(acc[mi][ni], alf, bh[ni]);
                }
            }
        }
        __syncthreads();
    }
    #undef LOADT

    // epilogue: c0,c1 -> row lane>>2 ; c2,c3 -> row+8 ; cols 2*(lane&3)+{0,1}
    #pragma unroll
    for (int mi = 0; mi < 4; mi++) {
        #pragma unroll
        for (int ni = 0; ni < 4; ni++) {
            int row = m0 + wm * 64 + mi * 16 + (lane >> 2);
            int col = n0 + wn * 32 + ni * 8 + 2 * (lane & 3);
            float b0 = 0.f, b1 = 0.f;
            if (bias) { b0 = bias[col]; b1 = bias[col + 1]; }
            #pragma unroll
            for (int h = 0; h < 2; h++) {
                float v0 = acc[mi][ni][2 * h + 0] + b0;
                float v1 = acc[mi][ni][2 * h + 1] + b1;
                if (ACT == 1) { v0 = fmaxf(v0, 0.f); v1 = fmaxf(v1, 0.f); }
                else if (ACT == 2) {
                    v0 = 1.0f / (1.0f + expf(-v0));
                    v1 = 1.0f / (1.0f + expf(-v1));
                }
                size_t o = (size_t)(row + 8 * h) * ldc + col;
                *(float2*)&C[o] = make_float2(v0, v1);
                if (C2) { C2[o] = v0; C2[o + 1] = v1; }
            }
        }
    }
}

// ================= hi/lo bf16 conversions =================
__global__ __launch_bounds__(256) void conv_a_kernel(const float* __restrict__ src,
                                                     __nv_bfloat16* __restrict__ h,
                                                     __nv_bfloat16* __restrict__ l, size_t n) {
    size_t stride = (size_t)gridDim.x * blockDim.x;
    for (size_t i = (size_t)blockIdx.x * blockDim.x + threadIdx.x; i < n; i += stride) {
        float a = src[i];
        __nv_bfloat16 bh = __float2bfloat16(a);
        h[i] = bh;
        l[i] = __float2bfloat16(a - __bfloat162float(bh));
    }
}
// transposed: src[R][C] fp32 -> dst[C][R] bf16 hi/lo
__global__ void conv_bt_kernel(const float* __restrict__ src,
                               __nv_bfloat16* __restrict__ h,
                               __nv_bfloat16* __restrict__ l, int R, int C) {
    __shared__ float t[32][33];
    int c = blockIdx.x * 32 + threadIdx.x;
    int r0 = blockIdx.y * 32;
    for (int dy = threadIdx.y; dy < 32; dy += 8)
        t[dy][threadIdx.x] = src[(size_t)(r0 + dy) * C + c];
    __syncthreads();
    int rr = r0 + threadIdx.x;
    int cc0 = blockIdx.x * 32;
    for (int dy = threadIdx.y; dy < 32; dy += 8) {
        float a = t[threadIdx.x][dy];
        __nv_bfloat16 bh = __float2bfloat16(a);
        size_t o = (size_t)(cc0 + dy) * R + rr;
        h[o] = bh;
        l[o] = __float2bfloat16(a - __bfloat162float(bh));
    }
}

// ================= reductions =================
__device__ __forceinline__ float blk_reduce(float v, int op) {
    __shared__ float sh[32];
    __syncthreads();
    int lane = threadIdx.x & 31, wid = threadIdx.x >> 5;
    #pragma unroll
    for (int o = 16; o > 0; o >>= 1) {
        float w = __shfl_down_sync(0xffffffffu, v, o);
        v = op ? fmaxf(v, w) : v + w;
    }
    if (lane == 0) sh[wid] = v;
    __syncthreads();
    int nw = blockDim.x >> 5;
    v = (threadIdx.x < nw) ? sh[threadIdx.x] : (op ? -1e30f : 0.0f);
    if (wid == 0) {
        #pragma unroll
        for (int o = 16; o > 0; o >>= 1) {
            float w = __shfl_down_sync(0xffffffffu, v, o);
            v = op ? fmaxf(v, w) : v + w;
        }
        if (lane == 0) sh[0] = v;
    }
    __syncthreads();
    return sh[0];
}

// normalize + optional raw copy + optional fused |dot| for loss_direct
__global__ __launch_bounds__(256) void normalize_rows(const float* __restrict__ in,
                                                      float* __restrict__ out,
                                                      float* __restrict__ raw_copy,
                                                      const float* __restrict__ dotw) {
    int row = blockIdx.x;
    const float* x = in + (size_t)row * DD;
    float vv[4];
    float s = 0.0f, d = 0.0f;
    #pragma unroll
    for (int i = 0; i < 4; i++) {
        int k = threadIdx.x + i * 256;
        float v = x[k];
        vv[i] = v;
        s += v * v;
        if (dotw) d += v * dotw[(size_t)row * DD + k];
    }
    float tot = blk_reduce(s, 0);
    float inv = 1.0f / fmaxf(sqrtf(tot), EPSN);
    if (dotw) {
        float dt = blk_reduce(d, 0);
        if (threadIdx.x == 0) atomicAdd(&g_loss[2], (double)fabsf(dt * inv));
    }
    #pragma unroll
    for (int i = 0; i < 4; i++) {
        int k = threadIdx.x + i * 256;
        out[(size_t)row * DD + k] = vv[i] * inv;
        if (raw_copy) raw_copy[(size_t)row * DD + k] = vv[i];
    }
}

__global__ void zero_kernel() {
    int i0 = blockIdx.x * blockDim.x + threadIdx.x;
    int stride = gridDim.x * blockDim.x;
    for (int i = i0; i < NCC * DD; i += stride) g_sums[i] = 0.0f;
    if (i0 < NCC) g_counts[i0] = 0.0f;
    if (i0 < 3) g_loss[i0] = 0.0;
}

__global__ __launch_bounds__(256) void argmax_kernel() {
    int row = blockIdx.x;
    const float* s = g_S + (size_t)row * NCC;
    int tid = threadIdx.x;
    __shared__ float sv[256];
    __shared__ int   si[256];
    {
        float best = -1e30f; int bidx = 0;
        for (int c = tid; c < NGC; c += 256) {
            float v = s[c];
            if (v > best) { best = v; bidx = c; }
        }
        sv[tid] = best; si[tid] = bidx;
        __syncthreads();
        for (int off = 128; off > 0; off >>= 1) {
            if (tid < off) {
                if (sv[tid + off] > sv[tid] ||
                    (sv[tid + off] == sv[tid] && si[tid + off] < si[tid])) {
                    sv[tid] = sv[tid + off]; si[tid] = si[tid + off];
                }
            }
            __syncthreads();
        }
        if (tid == 0) g_idx[row] = si[0];
        __syncthreads();
    }
    {
        float best = -1e30f; int bidx = 0;
        for (int c = tid; c < NLC; c += 256) {
            float v = s[NGC + c];
            if (v > best) { best = v; bidx = c; }
        }
        sv[tid] = best; si[tid] = bidx;
        __syncthreads();
        for (int off = 128; off > 0; off >>= 1) {
            if (tid < off) {
                if (sv[tid + off] > sv[tid] ||
                    (sv[tid + off] == sv[tid] && si[tid + off] < si[tid])) {
                    sv[tid] = sv[tid + off]; si[tid] = si[tid + off];
                }
            }
            __syncthreads();
        }
        if (tid == 0) g_idx[NROWS + row] = si[0];
    }
}

__global__ __launch_bounds__(256) void scatter_kernel(const float* __restrict__ unorm) {
    int row = blockIdx.x;
    int cg = g_idx[row];
    int cl = g_idx[NROWS + row] + NGC;
    const float* u = unorm + (size_t)row * DD;
    float* sg = g_sums + (size_t)cg * DD;
    float* sl = g_sums + (size_t)cl * DD;
    for (int k = threadIdx.x; k < DD; k += 256) {
        float v = u[k];
        atomicAdd(&sg[k], v);
        atomicAdd(&sl[k], v);
    }
    if (threadIdx.x == 0) {
        atomicAdd(&g_counts[cg], 1.0f);
        atomicAdd(&g_counts[cl], 1.0f);
    }
}

__global__ __launch_bounds__(256) void dict_update(const float* __restrict__ gdict,
                                                   const float* __restrict__ ldict) {
    int c = blockIdx.x;
    const float* d = (c < NGC) ? (gdict + (size_t)c * DD)
                               : (ldict + (size_t)(c - NGC) * DD);
    float m = (c < NGC) ? MOM_G : MOM_L;
    float cnt = g_counts[c];
    float invc = 1.0f / fmaxf(cnt, 1.0f);
    float vals[4];
    float s = 0.0f;
    #pragma unroll
    for (int i = 0; i < 4; i++) {
        int k = threadIdx.x + i * 256;
        float dv = d[k];
        float up = (cnt > 0.0f) ? (m * dv + (1.0f - m) * g_sums[(size_t)c * DD + k] * invc)
                                : dv;
        vals[i] = up;
        s += up * up;
    }
    float tot = blk_reduce(s, 0);
    float inv = 1.0f / fmaxf(sqrtf(tot), EPSN);
    #pragma unroll
    for (int i = 0; i < 4; i++) {
        int k = threadIdx.x + i * 256;
        g_comb[(size_t)c * DD + k] = vals[i] * inv;
    }
}

// fused: loss_g/loss_l partial sums + row softmax (in place)
__global__ __launch_bounds__(256) void softmax_loss_kernel() {
    int row = blockIdx.x;
    float* s = g_S + (size_t)row * NCC;
    int tid = threadIdx.x;
    float lv[5];
    float m = -1e30f, sg = 0.0f, sl = 0.0f;
    #pragma unroll
    for (int i = 0; i < 5; i++) {
        int c = tid + i * 256;
        lv[i] = s[c];
        m = fmaxf(m, lv[i]);
        if (c < NGC) sg += fabsf(lv[i]); else sl += fabsf(lv[i]);
    }
    float bg = blk_reduce(sg, 0);
    if (tid == 0) atomicAdd(&g_loss[0], (double)bg);
    float bl = blk_reduce(sl, 0);
    if (tid == 0) atomicAdd(&g_loss[1], (double)bl);
    float M = blk_reduce(m, 1);
    float sum = 0.0f;
    #pragma unroll
    for (int i = 0; i < 5; i++) { lv[i] = expf((lv[i] - M) * TEMP_INV); sum += lv[i]; }
    float S = blk_reduce(sum, 0);
    float inv = 1.0f / S;
    #pragma unroll
    for (int i = 0; i < 5; i++) s[tid + i * 256] = lv[i] * inv;
}

__global__ __launch_bounds__(256) void final_kernel(const float* __restrict__ z,
                                                    const float* __restrict__ gate,
                                                    const float* __restrict__ wu,
                                                    float* __restrict__ out) {
    size_t stride = (size_t)gridDim.x * blockDim.x;
    for (size_t i = (size_t)blockIdx.x * blockDim.x + threadIdx.x;
         i < (size_t)NROWS * DD; i += stride)
        out[i] = z[i] - gate[i] * wu[i];
}

__global__ void write_loss(float* out_loss) {
    if (threadIdx.x == 0 && blockIdx.x == 0) {
        double l = g_loss[0] / ((double)NROWS * NGC)
                 + g_loss[1] / ((double)NROWS * NLC)
                 + g_loss[2] / (double)NROWS;
        out_loss[0] = (float)l;
    }
}

// ================= host launch =================
extern "C" void kernel_launch(void* const* d_in, const int* in_sizes, int n_in,
                              void* d_out, int out_size) {
    const float* z     = (const float*)d_in[0];
    const float* u     = (const float*)d_in[1];
    const float* W1    = (const float*)d_in[2];
    const float* b1    = (const float*)d_in[3];
    const float* W2    = (const float*)d_in[4];
    const float* b2    = (const float*)d_in[5];
    const float* Wg    = (const float*)d_in[6];
    const float* bg    = (const float*)d_in[7];
    const float* gdict = (const float*)d_in[8];
    const float* ldict = (const float*)d_in[9];

    float* out        = (float*)d_out;
    float* out_zclean = out;
    float* out_loss   = out + (size_t)NROWS * DD;
    float* out_zproj  = out_loss + 1;
    float* out_u      = out_zproj + (size_t)NROWS * DD;

    float *hidden, *zproj, *unorm, *S, *comb;
    __nv_bfloat16 *Ah, *Al, *Bh, *Bl;
    cudaGetSymbolAddress((void**)&hidden, g_hidden);
    cudaGetSymbolAddress((void**)&zproj,  g_zproj);
    cudaGetSymbolAddress((void**)&unorm,  g_unorm);
    cudaGetSymbolAddress((void**)&S,      g_S);
    cudaGetSymbolAddress((void**)&comb,   g_comb);
    cudaGetSymbolAddress((void**)&Ah,     g_Ah);
    cudaGetSymbolAddress((void**)&Al,     g_Al);
    cudaGetSymbolAddress((void**)&Bh,     g_Bh);
    cudaGetSymbolAddress((void**)&Bl,     g_Bl);
    float* znorm = hidden;   // relu output dead after proj2 (bf16 copies consumed)
    float* wu    = unorm;    // unorm dead after its conversions + scatter
    float* gate  = hidden;   // znorm dead after conv + fused loss_direct

    const int SMEM = 8 * TILEB;   // 81920 B
    cudaFuncSetAttribute(bgemm<0>, cudaFuncAttributeMaxDynamicSharedMemorySize, SMEM);
    cudaFuncSetAttribute(bgemm<1>, cudaFuncAttributeMaxDynamicSharedMemorySize, SMEM);
    cudaFuncSetAttribute(bgemm<2>, cudaFuncAttributeMaxDynamicSharedMemorySize, SMEM);

    const dim3 TB(32, 8);
    const int MT = NROWS / 128;   // 256
    const size_t ND = (size_t)NROWS * DD;

    zero_kernel<<<1024, 256>>>();
    normalize_rows<<<NROWS, 256>>>(u, unorm, out_u, nullptr);

    // ---- projector ----
    conv_a_kernel<<<4096, 256>>>(z, Ah, Al, ND);
    conv_bt_kernel<<<dim3(DD / 32, DD / 32), TB>>>(W1, Bh, Bl, DD, DD);
    bgemm<1><<<dim3(DD / 128, MT), 256, SMEM>>>(Ah, Al, Bh, Bl, b1, hidden, nullptr,
                                                DD, DD, DD);
    conv_a_kernel<<<4096, 256>>>(hidden, Ah, Al, ND);
    conv_bt_kernel<<<dim3(DD / 32, DD / 32), TB>>>(W2, Bh, Bl, DD, DD);
    bgemm<0><<<dim3(DD / 128, MT), 256, SMEM>>>(Ah, Al, Bh, Bl, b2, zproj, out_zproj,
                                                DD, DD, DD);
    // znorm (overwrites hidden) + fused loss_direct dot vs unorm
    normalize_rows<<<NROWS, 256>>>(zproj, znorm, nullptr, unorm);

    // ---- sim vs OLD dicts (single merged GEMM, N=1280) ----
    conv_a_kernel<<<4096, 256>>>(unorm, Ah, Al, ND);
    conv_a_kernel<<<2048, 256>>>(gdict, Bh, Bl, (size_t)NGC * DD);
    conv_a_kernel<<<1024, 256>>>(ldict, Bh + (size_t)NGC * DD, Bl + (size_t)NGC * DD,
                                 (size_t)NLC * DD);
    bgemm<0><<<dim3(NCC / 128, MT), 256, SMEM>>>(Ah, Al, Bh, Bl, nullptr, S, nullptr,
                                                 NCC, DD, NCC);
    argmax_kernel<<<NROWS, 256>>>();
    scatter_kernel<<<NROWS, 256>>>(unorm);
    dict_update<<<NCC, 256>>>(gdict, ldict);

    // ---- logits vs UPDATED dicts -> losses -> softmax -> weighted_u ----
    conv_a_kernel<<<4096, 256>>>(znorm, Ah, Al, ND);
    conv_a_kernel<<<2048, 256>>>(comb, Bh, Bl, (size_t)NCC * DD);
    bgemm<0><<<dim3(NCC / 128, MT), 256, SMEM>>>(Ah, Al, Bh, Bl, nullptr, S, nullptr,
                                                 NCC, DD, NCC);
    softmax_loss_kernel<<<NROWS, 256>>>();
    conv_a_kernel<<<4096, 256>>>(S, Ah, Al, (size_t)NROWS * NCC);
    conv_bt_kernel<<<dim3(DD / 32, NCC / 32), TB>>>(comb, Bh, Bl, NCC, DD);
    bgemm<0><<<dim3(DD / 128, MT), 256, SMEM>>>(Ah, Al, Bh, Bl, nullptr, wu, nullptr,
                                                DD, NCC, DD);

    // ---- gate + final combine ----
    conv_a_kernel<<<4096, 256>>>(zproj, Ah, Al, ND);
    conv_bt_kernel<<<dim3(DD / 32, DD / 32), TB>>>(Wg, Bh, Bl, DD, DD);
    bgemm<2><<<dim3(DD / 128, MT), 256, SMEM>>>(Ah, Al, Bh, Bl, bg, gate, nullptr,
                                                DD, DD, DD);
    final_kernel<<<2048, 256>>>(z, gate, wu, out_zclean);
    write_loss<<<1, 32>>>(out_loss);
}

// round 9
// speedup vs baseline: 1.3036x; 1.3036x over previous
#include <cuda_runtime.h>
#include <cstdint>
#include <math.h>

// Problem constants
#define NROWS 32768        // B*L = 8*4096
#define DD    1024
#define NGC   1024
#define NLC   256
#define NCC   1280
#define MOM_G 0.999f
#define MOM_L 0.8f
#define TEMP_INV (1.0f/0.07f)
#define EPSN  1e-12f

// ================= scratch (device globals) =================
__device__ float g_hidden[NROWS * DD];   // relu -> znorm -> gate
__device__ float g_zproj [NROWS * DD];
__device__ float g_unorm [NROWS * DD];   // unorm -> wu
__device__ float g_S     [NROWS * NCC];
__device__ float g_comb  [NCC * DD];
__device__ float g_sums  [NCC * DD];     // sums -> combT
__device__ float g_Wt    [DD * DD];
__device__ float g_counts[NCC];
__device__ int   g_idx   [2 * NROWS];
__device__ double g_loss [3];

// ================= tf32 mma.sync GEMM =================
__device__ __forceinline__ uint32_t tf32_rn(float a) {
    uint32_t b; asm("cvt.rna.tf32.f32 %0, %1;" : "=r"(b) : "f"(a));
    return b;
}
__device__ __forceinline__ void mma_tf32(float c[4], uint32_t a0, uint32_t a1,
                                         uint32_t a2, uint32_t a3,
                                         uint32_t b0, uint32_t b1) {
    asm volatile("mma.sync.aligned.m16n8k8.row.col.f32.tf32.tf32.f32 "
        "{%0,%1,%2,%3}, {%4,%5,%6,%7}, {%8,%9}, {%0,%1,%2,%3};"
        : "+f"(c[0]), "+f"(c[1]), "+f"(c[2]), "+f"(c[3])
        : "r"(a0), "r"(a1), "r"(a2), "r"(a3), "r"(b0), "r"(b1));
}
#define CP16(dst_u32, src_ptr) \
    asm volatile("cp.async.cg.shared.global [%0], [%1], 16;" :: "r"(dst_u32), "l"(src_ptr))
#define CP_COMMIT() asm volatile("cp.async.commit_group;" ::: "memory")
#define CP_WAIT1()  asm volatile("cp.async.wait_group 1;" ::: "memory")
#define CP_WAIT0()  asm volatile("cp.async.wait_group 0;" ::: "memory")

#define TPAD 36   // floats per SMEM row (32 data + 4 pad)

// C[M,N] = A[M,K] @ B[N,K]^T, row-major. CTA 128x128, warp 64x32, BK=32.
// SPLIT=1: 3xTF32 (fp32-accurate, explicit cvt). SPLIT=0: raw fp32 bits (HW truncates).
// ACT: 0 none, 1 relu, 2 sigmoid. C2: optional scalar-store duplicate (unaligned ok).
template<int SPLIT, int ACT>
__global__ __launch_bounds__(256) void tgemm(
    const float* __restrict__ A, const float* __restrict__ B,
    const float* __restrict__ bias, float* __restrict__ C,
    float* __restrict__ C2, int N, int K, int ldc)
{
    extern __shared__ float sm[];
    float* As = sm;                    // [2][128][TPAD]
    float* Bs = sm + 2 * 128 * TPAD;   // [2][128][TPAD]
    const int tid = threadIdx.x;
    const int lane = tid & 31, wid = tid >> 5;
    const int wm = wid >> 2, wn = wid & 3;
    const int m0 = blockIdx.y * 128, n0 = blockIdx.x * 128;
    const uint32_t s_as = (uint32_t)__cvta_generic_to_shared(As);
    const uint32_t s_bs = (uint32_t)__cvta_generic_to_shared(Bs);
    const float* gA = A + (size_t)m0 * K;
    const float* gB = B + (size_t)n0 * K;
    const int NK = K / 32;

    float acc[4][4][4];
    #pragma unroll
    for (int i = 0; i < 4; i++)
        #pragma unroll
        for (int j = 0; j < 4; j++)
            #pragma unroll
            for (int q = 0; q < 4; q++) acc[i][j][q] = 0.0f;

    const int lr = tid >> 1;           // row 0..127
    const int lc = (tid & 1) << 4;     // col 0 or 16
    #define LOAD_TILE(kt, buf) do { \
        const float* asrc = gA + (size_t)lr * K + (kt) * 32 + lc; \
        const float* bsrc = gB + (size_t)lr * K + (kt) * 32 + lc; \
        uint32_t ad = s_as + (((buf) * 128 + lr) * TPAD + lc) * 4; \
        uint32_t bd = s_bs + (((buf) * 128 + lr) * TPAD + lc) * 4; \
        CP16(ad, asrc);      CP16(ad + 16, asrc + 4); \
        CP16(ad + 32, asrc + 8); CP16(ad + 48, asrc + 12); \
        CP16(bd, bsrc);      CP16(bd + 16, bsrc + 4); \
        CP16(bd + 32, bsrc + 8); CP16(bd + 48, bsrc + 12); \
    } while (0)

    LOAD_TILE(0, 0);
    CP_COMMIT();

    for (int kt = 0; kt < NK; kt++) {
        const int buf = kt & 1;
        if (kt + 1 < NK) { LOAD_TILE(kt + 1, (kt + 1) & 1); CP_COMMIT(); CP_WAIT1(); }
        else             { CP_WAIT0(); }
        __syncthreads();

        #pragma unroll
        for (int ks = 0; ks < 4; ks++) {
            const int k = ks * 8 + (lane & 3);
            uint32_t ah[4][4], al[4][4], bh[4][2], bl[4][2];
            #pragma unroll
            for (int mi = 0; mi < 4; mi++) {
                int row = wm * 64 + mi * 16 + (lane >> 2);
                const float* r0 = &As[(buf * 128 + row) * TPAD];
                const float* r1 = r0 + 8 * TPAD;
                float v0 = r0[k], v1 = r1[k], v2 = r0[k + 4], v3 = r1[k + 4];
                if (SPLIT) {
                    ah[mi][0] = tf32_rn(v0); ah[mi][1] = tf32_rn(v1);
                    ah[mi][2] = tf32_rn(v2); ah[mi][3] = tf32_rn(v3);
                    al[mi][0] = tf32_rn(v0 - __uint_as_float(ah[mi][0]));
                    al[mi][1] = tf32_rn(v1 - __uint_as_float(ah[mi][1]));
                    al[mi][2] = tf32_rn(v2 - __uint_as_float(ah[mi][2]));
                    al[mi][3] = tf32_rn(v3 - __uint_as_float(ah[mi][3]));
                } else {
                    ah[mi][0] = __float_as_uint(v0); ah[mi][1] = __float_as_uint(v1);
                    ah[mi][2] = __float_as_uint(v2); ah[mi][3] = __float_as_uint(v3);
                }
            }
            #pragma unroll
            for (int ni = 0; ni < 4; ni++) {
                int n = wn * 32 + ni * 8 + (lane >> 2);
                const float* r0 = &Bs[(buf * 128 + n) * TPAD];
                float w0 = r0[k], w1 = r0[k + 4];
                if (SPLIT) {
                    bh[ni][0] = tf32_rn(w0); bh[ni][1] = tf32_rn(w1);
                    bl[ni][0] = tf32_rn(w0 - __uint_as_float(bh[ni][0]));
                    bl[ni][1] = tf32_rn(w1 - __uint_as_float(bh[ni][1]));
                } else {
                    bh[ni][0] = __float_as_uint(w0); bh[ni][1] = __float_as_uint(w1);
                }
            }
            #pragma unroll
            for (int mi = 0; mi < 4; mi++)
                #pragma unroll
                for (int ni = 0; ni < 4; ni++) {
                    if (SPLIT) {
                        mma_tf32(acc[mi][ni], al[mi][0], al[mi][1], al[mi][2], al[mi][3],
                                 bh[ni][0], bh[ni][1]);
                        mma_tf32(acc[mi][ni], ah[mi][0], ah[mi][1], ah[mi][2], ah[mi][3],
                                 bl[ni][0], bl[ni][1]);
                    }
                    mma_tf32(acc[mi][ni], ah[mi][0], ah[mi][1], ah[mi][2], ah[mi][3],
                             bh[ni][0], bh[ni][1]);
                }
        }
        __syncthreads();
    }
    #undef LOAD_TILE

    // ---- epilogue ----
    #pragma unroll
    for (int mi = 0; mi < 4; mi++) {
        #pragma unroll
        for (int ni = 0; ni < 4; ni++) {
            int row = m0 + wm * 64 + mi * 16 + (lane >> 2);
            int col = n0 + wn * 32 + ni * 8 + 2 * (lane & 3);
            float b0 = 0.f, b1 = 0.f;
            if (bias) { b0 = bias[col]; b1 = bias[col + 1]; }
            #pragma unroll
            for (int h = 0; h < 2; h++) {
                float v0 = acc[mi][ni][2 * h + 0] + b0;
                float v1 = acc[mi][ni][2 * h + 1] + b1;
                if (ACT == 1) { v0 = fmaxf(v0, 0.f); v1 = fmaxf(v1, 0.f); }
                else if (ACT == 2) {
                    v0 = 1.0f / (1.0f + expf(-v0));
                    v1 = 1.0f / (1.0f + expf(-v1));
                }
                size_t o = (size_t)(row + 8 * h) * ldc + col;
                *(float2*)&C[o] = make_float2(v0, v1);
                if (C2) { C2[o] = v0; C2[o + 1] = v1; }
            }
        }
    }
}

// ================= transpose: out[C][R] = in[R][C] =================
__global__ void transpose_kernel(const float* __restrict__ in, float* __restrict__ out,
                                 int R, int C) {
    __shared__ float t[32][33];
    int c = blockIdx.x * 32 + threadIdx.x;
    int r0 = blockIdx.y * 32;
    for (int dy = threadIdx.y; dy < 32; dy += 8)
        t[dy][threadIdx.x] = in[(size_t)(r0 + dy) * C + c];
    __syncthreads();
    int rr = r0 + threadIdx.x;
    int cc0 = blockIdx.x * 32;
    for (int dy = threadIdx.y; dy < 32; dy += 8)
        out[(size_t)(cc0 + dy) * R + rr] = t[threadIdx.x][dy];
}

// ================= reductions =================
__device__ __forceinline__ float blk_reduce(float v, int op) {
    __shared__ float sh[32];
    __syncthreads();
    int lane = threadIdx.x & 31, wid = threadIdx.x >> 5;
    #pragma unroll
    for (int o = 16; o > 0; o >>= 1) {
        float w = __shfl_down_sync(0xffffffffu, v, o);
        v = op ? fmaxf(v, w) : v + w;
    }
    if (lane == 0) sh[wid] = v;
    __syncthreads();
    int nw = blockDim.x >> 5;
    v = (threadIdx.x < nw) ? sh[threadIdx.x] : (op ? -1e30f : 0.0f);
    if (wid == 0) {
        #pragma unroll
        for (int o = 16; o > 0; o >>= 1) {
            float w = __shfl_down_sync(0xffffffffu, v, o);
            v = op ? fmaxf(v, w) : v + w;
        }
        if (lane == 0) sh[0] = v;
    }
    __syncthreads();
    return sh[0];
}

// normalize + optional raw copy + optional fused |dot| accumulation (loss_direct)
__global__ __launch_bounds__(256) void normalize_rows(const float* __restrict__ in,
                                                      float* __restrict__ out,
                                                      float* __restrict__ raw_copy,
                                                      const float* __restrict__ dotw) {
    int row = blockIdx.x;
    const float* x = in + (size_t)row * DD;
    float vv[4];
    float s = 0.0f, d = 0.0f;
    #pragma unroll
    for (int i = 0; i < 4; i++) {
        int k = threadIdx.x + i * 256;
        float v = x[k];
        vv[i] = v;
        s += v * v;
        if (dotw) d += v * dotw[(size_t)row * DD + k];
    }
    float tot = blk_reduce(s, 0);
    float inv = 1.0f / fmaxf(sqrtf(tot), EPSN);
    if (dotw) {
        float dt = blk_reduce(d, 0);
        if (threadIdx.x == 0) atomicAdd(&g_loss[2], (double)fabsf(dt * inv));
    }
    #pragma unroll
    for (int i = 0; i < 4; i++) {
        int k = threadIdx.x + i * 256;
        out[(size_t)row * DD + k] = vv[i] * inv;
        if (raw_copy) raw_copy[(size_t)row * DD + k] = vv[i];
    }
}

__global__ void zero_kernel() {
    int i0 = blockIdx.x * blockDim.x + threadIdx.x;
    int stride = gridDim.x * blockDim.x;
    for (int i = i0; i < NCC * DD; i += stride) g_sums[i] = 0.0f;
    if (i0 < NCC) g_counts[i0] = 0.0f;
    if (i0 < 3) g_loss[i0] = 0.0;
}

__global__ __launch_bounds__(256) void argmax_kernel() {
    int row = blockIdx.x;
    const float* s = g_S + (size_t)row * NCC;
    int tid = threadIdx.x;
    __shared__ float sv[256];
    __shared__ int   si[256];
    {
        float best = -1e30f; int bidx = 0;
        for (int c = tid; c < NGC; c += 256) {
            float v = s[c];
            if (v > best) { best = v; bidx = c; }
        }
        sv[tid] = best; si[tid] = bidx;
        __syncthreads();
        for (int off = 128; off > 0; off >>= 1) {
            if (tid < off) {
                if (sv[tid + off] > sv[tid] ||
                    (sv[tid + off] == sv[tid] && si[tid + off] < si[tid])) {
                    sv[tid] = sv[tid + off]; si[tid] = si[tid + off];
                }
            }
            __syncthreads();
        }
        if (tid == 0) g_idx[row] = si[0];
        __syncthreads();
    }
    {
        float best = -1e30f; int bidx = 0;
        for (int c = tid; c < NLC; c += 256) {
            float v = s[NGC + c];
            if (v > best) { best = v; bidx = c; }
        }
        sv[tid] = best; si[tid] = bidx;
        __syncthreads();
        for (int off = 128; off > 0; off >>= 1) {
            if (tid < off) {
                if (sv[tid + off] > sv[tid] ||
                    (sv[tid + off] == sv[tid] && si[tid + off] < si[tid])) {
                    sv[tid] = sv[tid + off]; si[tid] = si[tid + off];
                }
            }
            __syncthreads();
        }
        if (tid == 0) g_idx[NROWS + row] = si[0];
    }
}

__global__ __launch_bounds__(256) void scatter_kernel(const float* __restrict__ unorm) {
    int row = blockIdx.x;
    int cg = g_idx[row];
    int cl = g_idx[NROWS + row] + NGC;
    const float* u = unorm + (size_t)row * DD;
    float* sg = g_sums + (size_t)cg * DD;
    float* sl = g_sums + (size_t)cl * DD;
    for (int k = threadIdx.x; k < DD; k += 256) {
        float v = u[k];
        atomicAdd(&sg[k], v);
        atomicAdd(&sl[k], v);
    }
    if (threadIdx.x == 0) {
        atomicAdd(&g_counts[cg], 1.0f);
        atomicAdd(&g_counts[cl], 1.0f);
    }
}

__global__ __launch_bounds__(256) void dict_update(const float* __restrict__ gdict,
                                                   const float* __restrict__ ldict) {
    int c = blockIdx.x;
    const float* d = (c < NGC) ? (gdict + (size_t)c * DD)
                               : (ldict + (size_t)(c - NGC) * DD);
    float m = (c < NGC) ? MOM_G : MOM_L;
    float cnt = g_counts[c];
    float invc = 1.0f / fmaxf(cnt, 1.0f);
    float vals[4];
    float s = 0.0f;
    #pragma unroll
    for (int i = 0; i < 4; i++) {
        int k = threadIdx.x + i * 256;
        float dv = d[k];
        float up = (cnt > 0.0f) ? (m * dv + (1.0f - m) * g_sums[(size_t)c * DD + k] * invc)
                                : dv;
        vals[i] = up;
        s += up * up;
    }
    float tot = blk_reduce(s, 0);
    float inv = 1.0f / fmaxf(sqrtf(tot), EPSN);
    #pragma unroll
    for (int i = 0; i < 4; i++) {
        int k = threadIdx.x + i * 256;
        g_comb[(size_t)c * DD + k] = vals[i] * inv;
    }
}

// fused: loss_g/loss_l |.| sums + row softmax (in place)
__global__ __launch_bounds__(256) void softmax_loss_kernel() {
    int row = blockIdx.x;
    float* s = g_S + (size_t)row * NCC;
    int tid = threadIdx.x;
    float lv[5];
    float m = -1e30f, sg = 0.0f, sl = 0.0f;
    #pragma unroll
    for (int i = 0; i < 5; i++) {
        int c = tid + i * 256;
        lv[i] = s[c];
        m = fmaxf(m, lv[i]);
        if (c < NGC) sg += fabsf(lv[i]); else sl += fabsf(lv[i]);
    }
    float bg = blk_reduce(sg, 0);
    if (tid == 0) atomicAdd(&g_loss[0], (double)bg);
    float bl = blk_reduce(sl, 0);
    if (tid == 0) atomicAdd(&g_loss[1], (double)bl);
    float M = blk_reduce(m, 1);
    float sum = 0.0f;
    #pragma unroll
    for (int i = 0; i < 5; i++) { lv[i] = expf((lv[i] - M) * TEMP_INV); sum += lv[i]; }
    float S = blk_reduce(sum, 0);
    float inv = 1.0f / S;
    #pragma unroll
    for (int i = 0; i < 5; i++) s[tid + i * 256] = lv[i] * inv;
}

__global__ __launch_bounds__(256) void final_kernel(const float* __restrict__ z,
                                                    const float* __restrict__ gate,
                                                    const float* __restrict__ wu,
                                                    float* __restrict__ out) {
    size_t stride = (size_t)gridDim.x * blockDim.x;
    for (size_t i = (size_t)blockIdx.x * blockDim.x + threadIdx.x;
         i < (size_t)NROWS * DD; i += stride)
        out[i] = z[i] - gate[i] * wu[i];
}

__global__ void write_loss(float* out_loss) {
    if (threadIdx.x == 0 && blockIdx.x == 0) {
        double l = g_loss[0] / ((double)NROWS * NGC)
                 + g_loss[1] / ((double)NROWS * NLC)
                 + g_loss[2] / (double)NROWS;
        out_loss[0] = (float)l;
    }
}

// ================= host launch =================
extern "C" void kernel_launch(void* const* d_in, const int* in_sizes, int n_in,
                              void* d_out, int out_size) {
    const float* z     = (const float*)d_in[0];
    const float* u     = (const float*)d_in[1];
    const float* W1    = (const float*)d_in[2];
    const float* b1    = (const float*)d_in[3];
    const float* W2    = (const float*)d_in[4];
    const float* b2    = (const float*)d_in[5];
    const float* Wg    = (const float*)d_in[6];
    const float* bg    = (const float*)d_in[7];
    const float* gdict = (const float*)d_in[8];
    const float* ldict = (const float*)d_in[9];

    float* out        = (float*)d_out;
    float* out_zclean = out;
    float* out_loss   = out + (size_t)NROWS * DD;
    float* out_zproj  = out_loss + 1;
    float* out_u      = out_zproj + (size_t)NROWS * DD;

    float *hidden, *zproj, *unorm, *S, *comb, *sums, *Wt;
    cudaGetSymbolAddress((void**)&hidden, g_hidden);
    cudaGetSymbolAddress((void**)&zproj,  g_zproj);
    cudaGetSymbolAddress((void**)&unorm,  g_unorm);
    cudaGetSymbolAddress((void**)&S,      g_S);
    cudaGetSymbolAddress((void**)&comb,   g_comb);
    cudaGetSymbolAddress((void**)&sums,   g_sums);
    cudaGetSymbolAddress((void**)&Wt,     g_Wt);
    float* znorm = hidden;   // relu output dead after proj2
    float* wu    = unorm;    // unorm dead after scatter + fused loss_direct
    float* gate  = hidden;   // znorm dead after logits GEMM + fused dot
    float* combT = sums;     // sums dead after dict_update

    const int SMEM = 2 * 2 * 128 * TPAD * 4;   // 73728 B
    cudaFuncSetAttribute(tgemm<0,0>, cudaFuncAttributeMaxDynamicSharedMemorySize, SMEM);
    cudaFuncSetAttribute(tgemm<0,2>, cudaFuncAttributeMaxDynamicSharedMemorySize, SMEM);
    cudaFuncSetAttribute(tgemm<1,0>, cudaFuncAttributeMaxDynamicSharedMemorySize, SMEM);
    cudaFuncSetAttribute(tgemm<1,1>, cudaFuncAttributeMaxDynamicSharedMemorySize, SMEM);

    const dim3 TB(32, 8);
    const int MT = NROWS / 128;   // 256

    zero_kernel<<<1024, 256>>>();
    normalize_rows<<<NROWS, 256>>>(u, unorm, out_u, nullptr);

    // projector (3xTF32 split: z_proj is a direct output); zproj copy fused via C2
    transpose_kernel<<<dim3(DD / 32, DD / 32), TB>>>(W1, Wt, DD, DD);
    tgemm<1,1><<<dim3(DD / 128, MT), 256, SMEM>>>(z, Wt, b1, hidden, nullptr, DD, DD, DD);
    transpose_kernel<<<dim3(DD / 32, DD / 32), TB>>>(W2, Wt, DD, DD);
    tgemm<1,0><<<dim3(DD / 128, MT), 256, SMEM>>>(hidden, Wt, b2, zproj, out_zproj,
                                                  DD, DD, DD);
    // znorm (overwrites hidden) + fused loss_direct |dot(znorm, unorm)|
    normalize_rows<<<NROWS, 256>>>(zproj, znorm, nullptr, unorm);

    // sim vs OLD dicts (truncated tf32; consumer argmax)
    tgemm<0,0><<<dim3(NGC / 128, MT), 256, SMEM>>>(unorm, gdict, nullptr, S, nullptr,
                                                   NGC, DD, NCC);
    tgemm<0,0><<<dim3(NLC / 128, MT), 256, SMEM>>>(unorm, ldict, nullptr, S + NGC, nullptr,
                                                   NLC, DD, NCC);
    argmax_kernel<<<NROWS, 256>>>();
    scatter_kernel<<<NROWS, 256>>>(unorm);
    dict_update<<<NCC, 256>>>(gdict, ldict);

    // logits vs UPDATED dicts -> fused losses+softmax -> weighted_u
    tgemm<0,0><<<dim3(NCC / 128, MT), 256, SMEM>>>(znorm, comb, nullptr, S, nullptr,
                                                   NCC, DD, NCC);
    softmax_loss_kernel<<<NROWS, 256>>>();
    transpose_kernel<<<dim3(DD / 32, NCC / 32), TB>>>(comb, combT, NCC, DD);
    tgemm<0,0><<<dim3(DD / 128, MT), 256, SMEM>>>(S, combT, nullptr, wu, nullptr,
                                                  DD, NCC, DD);

    // gate + final combine
    transpose_kernel<<<dim3(DD / 32, DD / 32), TB>>>(Wg, Wt, DD, DD);
    tgemm<0,2><<<dim3(DD / 128, MT), 256, SMEM>>>(zproj, Wt, bg, gate, nullptr,
                                                  DD, DD, DD);
    final_kernel<<<2048, 256>>>(z, gate, wu, out_zclean);
    write_loss<<<1, 32>>>(out_loss);
}

// round 10
// speedup vs baseline: 1.5450x; 1.1851x over previous
#include <cuda_runtime.h>
#include <cuda_bf16.h>
#include <cstdint>
#include <math.h>

// Problem constants
#define NROWS 32768        // B*L = 8*4096
#define DD    1024
#define NGC   1024
#define NLC   256
#define NCC   1280
#define MOM_G 0.999f
#define MOM_L 0.8f
#define TEMP_INV (1.0f/0.07f)
#define EPSN  1e-12f

// ================= scratch (device globals) =================
__device__ float g_hidden[NROWS * DD];   // relu -> znorm -> gate
__device__ float g_zproj [NROWS * DD];
__device__ float g_unorm [NROWS * DD];   // unorm -> wu
__device__ float g_S     [NROWS * NCC];
__device__ float g_comb  [NCC * DD];
__device__ float g_sums  [NCC * DD];     // sums -> combT
__device__ float g_Wt    [DD * DD];
__device__ float g_counts[NCC];
__device__ int   g_idx   [2 * NROWS];
__device__ double g_loss [3];
// bf16 hi/lo staging (projector only)
__device__ __nv_bfloat16 g_Ah[(size_t)NROWS * DD];
__device__ __nv_bfloat16 g_Al[(size_t)NROWS * DD];
__device__ __nv_bfloat16 g_Bh[(size_t)DD * DD];
__device__ __nv_bfloat16 g_Bl[(size_t)DD * DD];

// ================= common PTX helpers =================
__device__ __forceinline__ uint32_t tf32_rn(float a) {
    uint32_t b; asm("cvt.rna.tf32.f32 %0, %1;" : "=r"(b) : "f"(a));
    return b;
}
__device__ __forceinline__ void mma_tf32(float c[4], uint32_t a0, uint32_t a1,
                                         uint32_t a2, uint32_t a3,
                                         uint32_t b0, uint32_t b1) {
    asm volatile("mma.sync.aligned.m16n8k8.row.col.f32.tf32.tf32.f32 "
        "{%0,%1,%2,%3}, {%4,%5,%6,%7}, {%8,%9}, {%0,%1,%2,%3};"
        : "+f"(c[0]), "+f"(c[1]), "+f"(c[2]), "+f"(c[3])
        : "r"(a0), "r"(a1), "r"(a2), "r"(a3), "r"(b0), "r"(b1));
}
__device__ __forceinline__ void ldsm4(uint32_t r[4], uint32_t addr) {
    asm volatile("ldmatrix.sync.aligned.m8n8.x4.shared.b16 {%0,%1,%2,%3}, [%4];"
        : "=r"(r[0]), "=r"(r[1]), "=r"(r[2]), "=r"(r[3]) : "r"(addr));
}
__device__ __forceinline__ void mma_bf16(float c[4], const uint32_t a[4], const uint32_t b[2]) {
    asm volatile("mma.sync.aligned.m16n8k16.row.col.f32.bf16.bf16.f32 "
        "{%0,%1,%2,%3}, {%4,%5,%6,%7}, {%8,%9}, {%0,%1,%2,%3};"
        : "+f"(c[0]), "+f"(c[1]), "+f"(c[2]), "+f"(c[3])
        : "r"(a[0]), "r"(a[1]), "r"(a[2]), "r"(a[3]), "r"(b[0]), "r"(b[1]));
}
#define CP16(dst_u32, src_ptr) \
    asm volatile("cp.async.cg.shared.global [%0], [%1], 16;" :: "r"(dst_u32), "l"(src_ptr))
#define CP_COMMIT() asm volatile("cp.async.commit_group;" ::: "memory")
#define CP_WAIT1()  asm volatile("cp.async.wait_group 1;" ::: "memory")
#define CP_WAIT0()  asm volatile("cp.async.wait_group 0;" ::: "memory")

// ============ tf32 single-pass GEMM (cvt.rna fragments) ============
#define TPAD 36   // floats per SMEM row (32 data + 4 pad)
// C[M,N] = A[M,K] @ B[N,K]^T. CTA 128x128, warp 64x32, BK=32. ACT: 0 none, 2 sigmoid.
template<int ACT>
__global__ __launch_bounds__(256) void tgemm(
    const float* __restrict__ A, const float* __restrict__ B,
    const float* __restrict__ bias, float* __restrict__ C,
    int N, int K, int ldc)
{
    extern __shared__ float sm[];
    float* As = sm;                    // [2][128][TPAD]
    float* Bs = sm + 2 * 128 * TPAD;   // [2][128][TPAD]
    const int tid = threadIdx.x;
    const int lane = tid & 31, wid = tid >> 5;
    const int wm = wid >> 2, wn = wid & 3;
    const int m0 = blockIdx.y * 128, n0 = blockIdx.x * 128;
    const uint32_t s_as = (uint32_t)__cvta_generic_to_shared(As);
    const uint32_t s_bs = (uint32_t)__cvta_generic_to_shared(Bs);
    const float* gA = A + (size_t)m0 * K;
    const float* gB = B + (size_t)n0 * K;
    const int NK = K / 32;

    float acc[4][4][4];
    #pragma unroll
    for (int i = 0; i < 4; i++)
        #pragma unroll
        for (int j = 0; j < 4; j++)
            #pragma unroll
            for (int q = 0; q < 4; q++) acc[i][j][q] = 0.0f;

    const int lr = tid >> 1;
    const int lc = (tid & 1) << 4;
    #define LOAD_TILE(kt, buf) do { \
        const float* asrc = gA + (size_t)lr * K + (kt) * 32 + lc; \
        const float* bsrc = gB + (size_t)lr * K + (kt) * 32 + lc; \
        uint32_t ad = s_as + (((buf) * 128 + lr) * TPAD + lc) * 4; \
        uint32_t bd = s_bs + (((buf) * 128 + lr) * TPAD + lc) * 4; \
        CP16(ad, asrc);      CP16(ad + 16, asrc + 4); \
        CP16(ad + 32, asrc + 8); CP16(ad + 48, asrc + 12); \
        CP16(bd, bsrc);      CP16(bd + 16, bsrc + 4); \
        CP16(bd + 32, bsrc + 8); CP16(bd + 48, bsrc + 12); \
    } while (0)

    LOAD_TILE(0, 0);
    CP_COMMIT();

    for (int kt = 0; kt < NK; kt++) {
        const int buf = kt & 1;
        if (kt + 1 < NK) { LOAD_TILE(kt + 1, (kt + 1) & 1); CP_COMMIT(); CP_WAIT1(); }
        else             { CP_WAIT0(); }
        __syncthreads();

        #pragma unroll
        for (int ks = 0; ks < 4; ks++) {
            const int k = ks * 8 + (lane & 3);
            uint32_t ah[4][4], bh[4][2];
            #pragma unroll
            for (int mi = 0; mi < 4; mi++) {
                int row = wm * 64 + mi * 16 + (lane >> 2);
                const float* r0 = &As[(buf * 128 + row) * TPAD];
                const float* r1 = r0 + 8 * TPAD;
                ah[mi][0] = tf32_rn(r0[k]);     ah[mi][1] = tf32_rn(r1[k]);
                ah[mi][2] = tf32_rn(r0[k + 4]); ah[mi][3] = tf32_rn(r1[k + 4]);
            }
            #pragma unroll
            for (int ni = 0; ni < 4; ni++) {
                int n = wn * 32 + ni * 8 + (lane >> 2);
                const float* r0 = &Bs[(buf * 128 + n) * TPAD];
                bh[ni][0] = tf32_rn(r0[k]); bh[ni][1] = tf32_rn(r0[k + 4]);
            }
            #pragma unroll
            for (int mi = 0; mi < 4; mi++)
                #pragma unroll
                for (int ni = 0; ni < 4; ni++)
                    mma_tf32(acc[mi][ni], ah[mi][0], ah[mi][1], ah[mi][2], ah[mi][3],
                             bh[ni][0], bh[ni][1]);
        }
        __syncthreads();
    }
    #undef LOAD_TILE

    #pragma unroll
    for (int mi = 0; mi < 4; mi++) {
        #pragma unroll
        for (int ni = 0; ni < 4; ni++) {
            int row = m0 + wm * 64 + mi * 16 + (lane >> 2);
            int col = n0 + wn * 32 + ni * 8 + 2 * (lane & 3);
            float b0 = 0.f, b1 = 0.f;
            if (bias) { b0 = bias[col]; b1 = bias[col + 1]; }
            #pragma unroll
            for (int h = 0; h < 2; h++) {
                float v0 = acc[mi][ni][2 * h + 0] + b0;
                float v1 = acc[mi][ni][2 * h + 1] + b1;
                if (ACT == 2) {
                    v0 = 1.0f / (1.0f + expf(-v0));
                    v1 = 1.0f / (1.0f + expf(-v1));
                }
                *(float2*)&C[(size_t)(row + 8 * h) * ldc + col] = make_float2(v0, v1);
            }
        }
    }
}

// ============ bf16x3 GEMM (projector): C = A @ B^T ============
#define BPITCH 80             // bytes per SMEM row: 32 bf16 + 16B pad
#define TILEB  (128 * BPITCH)
template<int ACT>   // 0 none, 1 relu
__global__ __launch_bounds__(256, 2) void bgemm(
    const __nv_bfloat16* __restrict__ Ah, const __nv_bfloat16* __restrict__ Al,
    const __nv_bfloat16* __restrict__ Bh, const __nv_bfloat16* __restrict__ Bl,
    const float* __restrict__ bias, float* __restrict__ C,
    float* __restrict__ C2, int N, int K, int ldc)
{
    extern __shared__ char smc[];
    const int tid = threadIdx.x, lane = tid & 31, wid = tid >> 5;
    const int wm = wid >> 2, wn = wid & 3;
    const int m0 = blockIdx.y * 128, n0 = blockIdx.x * 128;
    const uint32_t sbase = (uint32_t)__cvta_generic_to_shared(smc);
    const int NK = K / 32;

    const int lr = tid >> 1;
    const int lco = (tid & 1) * 16;
    const __nv_bfloat16* pAh = Ah + (size_t)(m0 + lr) * K + lco;
    const __nv_bfloat16* pAl = Al + (size_t)(m0 + lr) * K + lco;
    const __nv_bfloat16* pBh = Bh + (size_t)(n0 + lr) * K + lco;
    const __nv_bfloat16* pBl = Bl + (size_t)(n0 + lr) * K + lco;
    const uint32_t dbase = sbase + lr * BPITCH + (tid & 1) * 32;

    #define LOADT(kt, buf) do { \
        int ko = (kt) * 32; \
        uint32_t d = dbase + (buf) * 4 * TILEB; \
        CP16(d,                 pAh + ko); CP16(d + 16,             pAh + ko + 8); \
        CP16(d + TILEB,         pAl + ko); CP16(d + TILEB + 16,     pAl + ko + 8); \
        CP16(d + 2 * TILEB,     pBh + ko); CP16(d + 2 * TILEB + 16, pBh + ko + 8); \
        CP16(d + 3 * TILEB,     pBl + ko); CP16(d + 3 * TILEB + 16, pBl + ko + 8); \
    } while (0)

    float acc[4][4][4];
    #pragma unroll
    for (int i = 0; i < 4; i++)
        #pragma unroll
        for (int j = 0; j < 4; j++)
            #pragma unroll
            for (int q = 0; q < 4; q++) acc[i][j][q] = 0.0f;

    LOADT(0, 0);
    CP_COMMIT();

    const int g = lane >> 3, l7 = lane & 7;
    for (int kt = 0; kt < NK; kt++) {
        const int buf = kt & 1;
        if (kt + 1 < NK) { LOADT(kt + 1, buf ^ 1); CP_COMMIT(); CP_WAIT1(); }
        else             { CP_WAIT0(); }
        __syncthreads();

        const uint32_t sA  = sbase + buf * 4 * TILEB;
        const uint32_t sAl = sA + TILEB;
        const uint32_t sB  = sA + 2 * TILEB;
        const uint32_t sBl = sA + 3 * TILEB;

        #pragma unroll
        for (int ks = 0; ks < 2; ks++) {
            uint32_t bh[4][2], bl[4][2];
            #pragma unroll
            for (int nj = 0; nj < 2; nj++) {
                uint32_t nrow = wn * 32 + nj * 16 + (g >> 1) * 8 + l7;
                uint32_t kb = ks * 32 + (g & 1) * 16;
                uint32_t r[4];
                ldsm4(r, sB + nrow * BPITCH + kb);
                bh[nj * 2 + 0][0] = r[0]; bh[nj * 2 + 0][1] = r[1];
                bh[nj * 2 + 1][0] = r[2]; bh[nj * 2 + 1][1] = r[3];
                ldsm4(r, sBl + nrow * BPITCH + kb);
                bl[nj * 2 + 0][0] = r[0]; bl[nj * 2 + 0][1] = r[1];
                bl[nj * 2 + 1][0] = r[2]; bl[nj * 2 + 1][1] = r[3];
            }
            #pragma unroll
            for (int mi = 0; mi < 4; mi++) {
                uint32_t arow = wm * 64 + mi * 16 + (g & 1) * 8 + l7;
                uint32_t kb = ks * 32 + (g >> 1) * 16;
                uint32_t ahf[4], alf[4];
                ldsm4(ahf, sA  + arow * BPITCH + kb);
                ldsm4(alf, sAl + arow * BPITCH + kb);
                #pragma unroll
                for (int ni = 0; ni < 4; ni++) {
                    mma_bf16(acc[mi][ni], ahf, bh[ni]);
                    mma_bf16(acc[mi][ni], ahf, bl[ni]);
                    mma_bf16(acc[mi][ni], alf, bh[ni]);
                }
            }
        }
        __syncthreads();
    }
    #undef LOADT

    #pragma unroll
    for (int mi = 0; mi < 4; mi++) {
        #pragma unroll
        for (int ni = 0; ni < 4; ni++) {
            int row = m0 + wm * 64 + mi * 16 + (lane >> 2);
            int col = n0 + wn * 32 + ni * 8 + 2 * (lane & 3);
            float b0 = 0.f, b1 = 0.f;
            if (bias) { b0 = bias[col]; b1 = bias[col + 1]; }
            #pragma unroll
            for (int h = 0; h < 2; h++) {
                float v0 = acc[mi][ni][2 * h + 0] + b0;
                float v1 = acc[mi][ni][2 * h + 1] + b1;
                if (ACT == 1) { v0 = fmaxf(v0, 0.f); v1 = fmaxf(v1, 0.f); }
                size_t o = (size_t)(row + 8 * h) * ldc + col;
                *(float2*)&C[o] = make_float2(v0, v1);
                if (C2) { C2[o] = v0; C2[o + 1] = v1; }
            }
        }
    }
}

// ================= hi/lo bf16 conversions =================
__global__ __launch_bounds__(256) void conv_a_kernel(const float4* __restrict__ src,
                                                     __nv_bfloat162* __restrict__ h,
                                                     __nv_bfloat162* __restrict__ l,
                                                     size_t n4) {
    size_t stride = (size_t)gridDim.x * blockDim.x;
    for (size_t i = (size_t)blockIdx.x * blockDim.x + threadIdx.x; i < n4; i += stride) {
        float4 v = src[i];
        __nv_bfloat16 h0 = __float2bfloat16(v.x), h1 = __float2bfloat16(v.y);
        __nv_bfloat16 h2 = __float2bfloat16(v.z), h3 = __float2bfloat16(v.w);
        h[2 * i]     = __nv_bfloat162(h0, h1);
        h[2 * i + 1] = __nv_bfloat162(h2, h3);
        l[2 * i]     = __nv_bfloat162(__float2bfloat16(v.x - __bfloat162float(h0)),
                                      __float2bfloat16(v.y - __bfloat162float(h1)));
        l[2 * i + 1] = __nv_bfloat162(__float2bfloat16(v.z - __bfloat162float(h2)),
                                      __float2bfloat16(v.w - __bfloat162float(h3)));
    }
}
// transposed: src[R][C] fp32 -> dst[C][R] bf16 hi/lo
__global__ void conv_bt_kernel(const float* __restrict__ src,
                               __nv_bfloat16* __restrict__ h,
                               __nv_bfloat16* __restrict__ l, int R, int C) {
    __shared__ float t[32][33];
    int c = blockIdx.x * 32 + threadIdx.x;
    int r0 = blockIdx.y * 32;
    for (int dy = threadIdx.y; dy < 32; dy += 8)
        t[dy][threadIdx.x] = src[(size_t)(r0 + dy) * C + c];
    __syncthreads();
    int rr = r0 + threadIdx.x;
    int cc0 = blockIdx.x * 32;
    for (int dy = threadIdx.y; dy < 32; dy += 8) {
        float a = t[threadIdx.x][dy];
        __nv_bfloat16 bh = __float2bfloat16(a);
        size_t o = (size_t)(cc0 + dy) * R + rr;
        h[o] = bh;
        l[o] = __float2bfloat16(a - __bfloat162float(bh));
    }
}

// ================= transpose (fp32) =================
__global__ void transpose_kernel(const float* __restrict__ in, float* __restrict__ out,
                                 int R, int C) {
    __shared__ float t[32][33];
    int c = blockIdx.x * 32 + threadIdx.x;
    int r0 = blockIdx.y * 32;
    for (int dy = threadIdx.y; dy < 32; dy += 8)
        t[dy][threadIdx.x] = in[(size_t)(r0 + dy) * C + c];
    __syncthreads();
    int rr = r0 + threadIdx.x;
    int cc0 = blockIdx.x * 32;
    for (int dy = threadIdx.y; dy < 32; dy += 8)
        out[(size_t)(cc0 + dy) * R + rr] = t[threadIdx.x][dy];
}

// ================= reductions =================
__device__ __forceinline__ float blk_reduce(float v, int op) {
    __shared__ float sh[32];
    __syncthreads();
    int lane = threadIdx.x & 31, wid = threadIdx.x >> 5;
    #pragma unroll
    for (int o = 16; o > 0; o >>= 1) {
        float w = __shfl_down_sync(0xffffffffu, v, o);
        v = op ? fmaxf(v, w) : v + w;
    }
    if (lane == 0) sh[wid] = v;
    __syncthreads();
    int nw = blockDim.x >> 5;
    v = (threadIdx.x < nw) ? sh[threadIdx.x] : (op ? -1e30f : 0.0f);
    if (wid == 0) {
        #pragma unroll
        for (int o = 16; o > 0; o >>= 1) {
            float w = __shfl_down_sync(0xffffffffu, v, o);
            v = op ? fmaxf(v, w) : v + w;
        }
        if (lane == 0) sh[0] = v;
    }
    __syncthreads();
    return sh[0];
}

// normalize + optional raw copy + optional fused |dot| (loss_direct)
__global__ __launch_bounds__(256) void normalize_rows(const float* __restrict__ in,
                                                      float* __restrict__ out,
                                                      float* __restrict__ raw_copy,
                                                      const float* __restrict__ dotw) {
    int row = blockIdx.x;
    const float* x = in + (size_t)row * DD;
    float vv[4];
    float s = 0.0f, d = 0.0f;
    #pragma unroll
    for (int i = 0; i < 4; i++) {
        int k = threadIdx.x + i * 256;
        float v = x[k];
        vv[i] = v;
        s += v * v;
        if (dotw) d += v * dotw[(size_t)row * DD + k];
    }
    float tot = blk_reduce(s, 0);
    float inv = 1.0f / fmaxf(sqrtf(tot), EPSN);
    if (dotw) {
        float dt = blk_reduce(d, 0);
        if (threadIdx.x == 0) atomicAdd(&g_loss[2], (double)fabsf(dt * inv));
    }
    #pragma unroll
    for (int i = 0; i < 4; i++) {
        int k = threadIdx.x + i * 256;
        out[(size_t)row * DD + k] = vv[i] * inv;
        if (raw_copy) raw_copy[(size_t)row * DD + k] = vv[i];
    }
}

__global__ void zero_kernel() {
    int i0 = blockIdx.x * blockDim.x + threadIdx.x;
    int stride = gridDim.x * blockDim.x;
    for (int i = i0; i < NCC * DD; i += stride) g_sums[i] = 0.0f;
    if (i0 < NCC) g_counts[i0] = 0.0f;
    if (i0 < 3) g_loss[i0] = 0.0;
}

__global__ __launch_bounds__(256) void argmax_kernel() {
    int row = blockIdx.x;
    const float* s = g_S + (size_t)row * NCC;
    int tid = threadIdx.x;
    __shared__ float sv[256];
    __shared__ int   si[256];
    {
        float best = -1e30f; int bidx = 0;
        for (int c = tid; c < NGC; c += 256) {
            float v = s[c];
            if (v > best) { best = v; bidx = c; }
        }
        sv[tid] = best; si[tid] = bidx;
        __syncthreads();
        for (int off = 128; off > 0; off >>= 1) {
            if (tid < off) {
                if (sv[tid + off] > sv[tid] ||
                    (sv[tid + off] == sv[tid] && si[tid + off] < si[tid])) {
                    sv[tid] = sv[tid + off]; si[tid] = si[tid + off];
                }
            }
            __syncthreads();
        }
        if (tid == 0) g_idx[row] = si[0];
        __syncthreads();
    }
    {
        float best = -1e30f; int bidx = 0;
        for (int c = tid; c < NLC; c += 256) {
            float v = s[NGC + c];
            if (v > best) { best = v; bidx = c; }
        }
        sv[tid] = best; si[tid] = bidx;
        __syncthreads();
        for (int off = 128; off > 0; off >>= 1) {
            if (tid < off) {
                if (sv[tid + off] > sv[tid] ||
                    (sv[tid + off] == sv[tid] && si[tid + off] < si[tid])) {
                    sv[tid] = sv[tid + off]; si[tid] = si[tid + off];
                }
            }
            __syncthreads();
        }
        if (tid == 0) g_idx[NROWS + row] = si[0];
    }
}

__global__ __launch_bounds__(256) void scatter_kernel(const float* __restrict__ unorm) {
    int row = blockIdx.x;
    int cg = g_idx[row];
    int cl = g_idx[NROWS + row] + NGC;
    const float* u = unorm + (size_t)row * DD;
    float* sg = g_sums + (size_t)cg * DD;
    float* sl = g_sums + (size_t)cl * DD;
    for (int k = threadIdx.x; k < DD; k += 256) {
        float v = u[k];
        atomicAdd(&sg[k], v);
        atomicAdd(&sl[k], v);
    }
    if (threadIdx.x == 0) {
        atomicAdd(&g_counts[cg], 1.0f);
        atomicAdd(&g_counts[cl], 1.0f);
    }
}

__global__ __launch_bounds__(256) void dict_update(const float* __restrict__ gdict,
                                                   const float* __restrict__ ldict) {
    int c = blockIdx.x;
    const float* d = (c < NGC) ? (gdict + (size_t)c * DD)
                               : (ldict + (size_t)(c - NGC) * DD);
    float m = (c < NGC) ? MOM_G : MOM_L;
    float cnt = g_counts[c];
    float invc = 1.0f / fmaxf(cnt, 1.0f);
    float vals[4];
    float s = 0.0f;
    #pragma unroll
    for (int i = 0; i < 4; i++) {
        int k = threadIdx.x + i * 256;
        float dv = d[k];
        float up = (cnt > 0.0f) ? (m * dv + (1.0f - m) * g_sums[(size_t)c * DD + k] * invc)
                                : dv;
        vals[i] = up;
        s += up * up;
    }
    float tot = blk_reduce(s, 0);
    float inv = 1.0f / fmaxf(sqrtf(tot), EPSN);
    #pragma unroll
    for (int i = 0; i < 4; i++) {
        int k = threadIdx.x + i * 256;
        g_comb[(size_t)c * DD + k] = vals[i] * inv;
    }
}

// fused: loss_g/loss_l |.| sums + row softmax (in place)
__global__ __launch_bounds__(256) void softmax_loss_kernel() {
    int row = blockIdx.x;
    float* s = g_S + (size_t)row * NCC;
    int tid = threadIdx.x;
    float lv[5];
    float m = -1e30f, sg = 0.0f, sl = 0.0f;
    #pragma unroll
    for (int i = 0; i < 5; i++) {
        int c = tid + i * 256;
        lv[i] = s[c];
        m = fmaxf(m, lv[i]);
        if (c < NGC) sg += fabsf(lv[i]); else sl += fabsf(lv[i]);
    }
    float bg = blk_reduce(sg, 0);
    if (tid == 0) atomicAdd(&g_loss[0], (double)bg);
    float bl = blk_reduce(sl, 0);
    if (tid == 0) atomicAdd(&g_loss[1], (double)bl);
    float M = blk_reduce(m, 1);
    float sum = 0.0f;
    #pragma unroll
    for (int i = 0; i < 5; i++) { lv[i] = expf((lv[i] - M) * TEMP_INV); sum += lv[i]; }
    float S = blk_reduce(sum, 0);
    float inv = 1.0f / S;
    #pragma unroll
    for (int i = 0; i < 5; i++) s[tid + i * 256] = lv[i] * inv;
}

__global__ __launch_bounds__(256) void final_kernel(const float* __restrict__ z,
                                                    const float* __restrict__ gate,
                                                    const float* __restrict__ wu,
                                                    float* __restrict__ out) {
    size_t stride = (size_t)gridDim.x * blockDim.x;
    for (size_t i = (size_t)blockIdx.x * blockDim.x + threadIdx.x;
         i < (size_t)NROWS * DD; i += stride)
        out[i] = z[i] - gate[i] * wu[i];
}

__global__ void write_loss(float* out_loss) {
    if (threadIdx.x == 0 && blockIdx.x == 0) {
        double l = g_loss[0] / ((double)NROWS * NGC)
                 + g_loss[1] / ((double)NROWS * NLC)
                 + g_loss[2] / (double)NROWS;
        out_loss[0] = (float)l;
    }
}

// ================= host launch =================
extern "C" void kernel_launch(void* const* d_in, const int* in_sizes, int n_in,
                              void* d_out, int out_size) {
    const float* z     = (const float*)d_in[0];
    const float* u     = (const float*)d_in[1];
    const float* W1    = (const float*)d_in[2];
    const float* b1    = (const float*)d_in[3];
    const float* W2    = (const float*)d_in[4];
    const float* b2    = (const float*)d_in[5];
    const float* Wg    = (const float*)d_in[6];
    const float* bg    = (const float*)d_in[7];
    const float* gdict = (const float*)d_in[8];
    const float* ldict = (const float*)d_in[9];

    float* out        = (float*)d_out;
    float* out_zclean = out;
    float* out_loss   = out + (size_t)NROWS * DD;
    float* out_zproj  = out_loss + 1;
    float* out_u      = out_zproj + (size_t)NROWS * DD;

    float *hidden, *zproj, *unorm, *S, *comb, *sums, *Wt;
    __nv_bfloat16 *Ah, *Al, *Bh, *Bl;
    cudaGetSymbolAddress((void**)&hidden, g_hidden);
    cudaGetSymbolAddress((void**)&zproj,  g_zproj);
    cudaGetSymbolAddress((void**)&unorm,  g_unorm);
    cudaGetSymbolAddress((void**)&S,      g_S);
    cudaGetSymbolAddress((void**)&comb,   g_comb);
    cudaGetSymbolAddress((void**)&sums,   g_sums);
    cudaGetSymbolAddress((void**)&Wt,     g_Wt);
    cudaGetSymbolAddress((void**)&Ah,     g_Ah);
    cudaGetSymbolAddress((void**)&Al,     g_Al);
    cudaGetSymbolAddress((void**)&Bh,     g_Bh);
    cudaGetSymbolAddress((void**)&Bl,     g_Bl);
    float* znorm = hidden;   // hidden fp32 dead after conv_a extracts it
    float* wu    = unorm;    // unorm dead after scatter + fused loss_direct
    float* gate  = hidden;   // znorm dead after logits GEMM
    float* combT = sums;     // sums dead after dict_update

    const int SMEM_T = 2 * 2 * 128 * TPAD * 4;   // 73728 B
    const int SMEM_B = 8 * TILEB;                // 81920 B
    cudaFuncSetAttribute(tgemm<0>, cudaFuncAttributeMaxDynamicSharedMemorySize, SMEM_T);
    cudaFuncSetAttribute(tgemm<2>, cudaFuncAttributeMaxDynamicSharedMemorySize, SMEM_T);
    cudaFuncSetAttribute(bgemm<0>, cudaFuncAttributeMaxDynamicSharedMemorySize, SMEM_B);
    cudaFuncSetAttribute(bgemm<1>, cudaFuncAttributeMaxDynamicSharedMemorySize, SMEM_B);

    const dim3 TB(32, 8);
    const int MT = NROWS / 128;   // 256
    const size_t ND = (size_t)NROWS * DD;

    zero_kernel<<<1024, 256>>>();
    normalize_rows<<<NROWS, 256>>>(u, unorm, out_u, nullptr);

    // ---- projector: bf16x3 ----
    conv_a_kernel<<<2048, 256>>>((const float4*)z, (__nv_bfloat162*)Ah,
                                 (__nv_bfloat162*)Al, ND / 4);
    conv_bt_kernel<<<dim3(DD / 32, DD / 32), TB>>>(W1, Bh, Bl, DD, DD);
    bgemm<1><<<dim3(DD / 128, MT), 256, SMEM_B>>>(Ah, Al, Bh, Bl, b1, hidden, nullptr,
                                                  DD, DD, DD);
    conv_a_kernel<<<2048, 256>>>((const float4*)hidden, (__nv_bfloat162*)Ah,
                                 (__nv_bfloat162*)Al, ND / 4);
    conv_bt_kernel<<<dim3(DD / 32, DD / 32), TB>>>(W2, Bh, Bl, DD, DD);
    bgemm<0><<<dim3(DD / 128, MT), 256, SMEM_B>>>(Ah, Al, Bh, Bl, b2, zproj, out_zproj,
                                                  DD, DD, DD);
    // znorm (overwrites hidden) + fused loss_direct |dot(znorm, unorm)|
    normalize_rows<<<NROWS, 256>>>(zproj, znorm, nullptr, unorm);

    // ---- sim vs OLD dicts (tf32 rna) ----
    tgemm<0><<<dim3(NGC / 128, MT), 256, SMEM_T>>>(unorm, gdict, nullptr, S, NGC, DD, NCC);
    tgemm<0><<<dim3(NLC / 128, MT), 256, SMEM_T>>>(unorm, ldict, nullptr, S + NGC,
                                                   NLC, DD, NCC);
    argmax_kernel<<<NROWS, 256>>>();
    scatter_kernel<<<NROWS, 256>>>(unorm);
    dict_update<<<NCC, 256>>>(gdict, ldict);

    // ---- logits vs UPDATED dicts -> fused losses+softmax -> weighted_u ----
    tgemm<0><<<dim3(NCC / 128, MT), 256, SMEM_T>>>(znorm, comb, nullptr, S, NCC, DD, NCC);
    softmax_loss_kernel<<<NROWS, 256>>>();
    transpose_kernel<<<dim3(DD / 32, NCC / 32), TB>>>(comb, combT, NCC, DD);
    tgemm<0><<<dim3(DD / 128, MT), 256, SMEM_T>>>(S, combT, nullptr, wu, DD, NCC, DD);

    // ---- gate + final combine ----
    transpose_kernel<<<dim3(DD / 32, DD / 32), TB>>>(Wg, Wt, DD, DD);
    tgemm<2><<<dim3(DD / 128, MT), 256, SMEM_T>>>(zproj, Wt, bg, gate, DD, DD, DD);
    final_kernel<<<2048, 256>>>(z, gate, wu, out_zclean);
    write_loss<<<1, 32>>>(out_loss);
}

// round 11
// speedup vs baseline: 1.5919x; 1.0304x over previous
#include <cuda_runtime.h>
#include <cuda_bf16.h>
#include <cstdint>
#include <math.h>

// Problem constants
#define NROWS 32768        // B*L = 8*4096
#define DD    1024
#define NGC   1024
#define NLC   256
#define NCC   1280
#define MOM_G 0.999f
#define MOM_L 0.8f
#define TEMP_INV (1.0f/0.07f)
#define EPSN  1e-12f

// ================= scratch (device globals) =================
__device__ float g_gate  [NROWS * DD];
__device__ float g_zproj [NROWS * DD];
__device__ float g_unorm [NROWS * DD];   // unorm -> wu (alias)
__device__ float g_S     [NROWS * NCC];
__device__ float g_comb  [NCC * DD];
__device__ float g_sums  [NCC * DD];
__device__ float g_counts[NCC];
__device__ int   g_idx   [2 * NROWS];
__device__ double g_loss [3];
// bf16 hi/lo pairs
__device__ __nv_bfloat16 g_P1h[(size_t)NROWS * DD];    // z -> znorm
__device__ __nv_bfloat16 g_P1l[(size_t)NROWS * DD];
__device__ __nv_bfloat16 g_P2h[(size_t)NROWS * NCC];   // hidden -> S(softmax)
__device__ __nv_bfloat16 g_P2l[(size_t)NROWS * NCC];
__device__ __nv_bfloat16 g_P3h[(size_t)NROWS * DD];    // unorm
__device__ __nv_bfloat16 g_P3l[(size_t)NROWS * DD];
__device__ __nv_bfloat16 g_P4h[(size_t)NROWS * DD];    // zproj
__device__ __nv_bfloat16 g_P4l[(size_t)NROWS * DD];
__device__ __nv_bfloat16 g_Bh [(size_t)NCC * DD];      // B operand (sequential reuse)
__device__ __nv_bfloat16 g_Bl [(size_t)NCC * DD];

// ================= PTX helpers =================
__device__ __forceinline__ void ldsm4(uint32_t r[4], uint32_t addr) {
    asm volatile("ldmatrix.sync.aligned.m8n8.x4.shared.b16 {%0,%1,%2,%3}, [%4];"
        : "=r"(r[0]), "=r"(r[1]), "=r"(r[2]), "=r"(r[3]) : "r"(addr));
}
__device__ __forceinline__ void mma_bf16(float c[4], const uint32_t a[4], const uint32_t b[2]) {
    asm volatile("mma.sync.aligned.m16n8k16.row.col.f32.bf16.bf16.f32 "
        "{%0,%1,%2,%3}, {%4,%5,%6,%7}, {%8,%9}, {%0,%1,%2,%3};"
        : "+f"(c[0]), "+f"(c[1]), "+f"(c[2]), "+f"(c[3])
        : "r"(a[0]), "r"(a[1]), "r"(a[2]), "r"(a[3]), "r"(b[0]), "r"(b[1]));
}
#define CP16(dst_u32, src_ptr) \
    asm volatile("cp.async.cg.shared.global [%0], [%1], 16;" :: "r"(dst_u32), "l"(src_ptr))
#define CP_COMMIT() asm volatile("cp.async.commit_group;" ::: "memory")
#define CP_WAIT1()  asm volatile("cp.async.wait_group 1;" ::: "memory")
#define CP_WAIT0()  asm volatile("cp.async.wait_group 0;" ::: "memory")

__device__ __forceinline__ void split_bf16(float v, __nv_bfloat16& h, __nv_bfloat16& l) {
    h = __float2bfloat16(v);
    l = __float2bfloat16(v - __bfloat162float(h));
}

// ============ bf16x3 GEMM: C[M,N] = A[M,K] @ B[N,K]^T ============
#define BPITCH 80             // bytes per SMEM row: 32 bf16 + 16B pad
#define TILEB  (128 * BPITCH)
// ACT: 0 none, 1 relu, 2 sigmoid. C/C2/Ch/Cl all optional.
template<int ACT>
__global__ __launch_bounds__(256, 2) void bgemm(
    const __nv_bfloat16* __restrict__ Ah, const __nv_bfloat16* __restrict__ Al,
    const __nv_bfloat16* __restrict__ Bh, const __nv_bfloat16* __restrict__ Bl,
    const float* __restrict__ bias, float* __restrict__ C, float* __restrict__ C2,
    __nv_bfloat16* __restrict__ Ch, __nv_bfloat16* __restrict__ Cl,
    int N, int K, int ldc)
{
    extern __shared__ char smc[];
    const int tid = threadIdx.x, lane = tid & 31, wid = tid >> 5;
    const int wm = wid >> 2, wn = wid & 3;
    const int m0 = blockIdx.y * 128, n0 = blockIdx.x * 128;
    const uint32_t sbase = (uint32_t)__cvta_generic_to_shared(smc);
    const int NK = K / 32;

    const int lr = tid >> 1;
    const int lco = (tid & 1) * 16;
    const __nv_bfloat16* pAh = Ah + (size_t)(m0 + lr) * K + lco;
    const __nv_bfloat16* pAl = Al + (size_t)(m0 + lr) * K + lco;
    const __nv_bfloat16* pBh = Bh + (size_t)(n0 + lr) * K + lco;
    const __nv_bfloat16* pBl = Bl + (size_t)(n0 + lr) * K + lco;
    const uint32_t dbase = sbase + lr * BPITCH + (tid & 1) * 32;

    #define LOADT(kt, buf) do { \
        int ko = (kt) * 32; \
        uint32_t d = dbase + (buf) * 4 * TILEB; \
        CP16(d,                 pAh + ko); CP16(d + 16,             pAh + ko + 8); \
        CP16(d + TILEB,         pAl + ko); CP16(d + TILEB + 16,     pAl + ko + 8); \
        CP16(d + 2 * TILEB,     pBh + ko); CP16(d + 2 * TILEB + 16, pBh + ko + 8); \
        CP16(d + 3 * TILEB,     pBl + ko); CP16(d + 3 * TILEB + 16, pBl + ko + 8); \
    } while (0)

    float acc[4][4][4];
    #pragma unroll
    for (int i = 0; i < 4; i++)
        #pragma unroll
        for (int j = 0; j < 4; j++)
            #pragma unroll
            for (int q = 0; q < 4; q++) acc[i][j][q] = 0.0f;

    LOADT(0, 0);
    CP_COMMIT();

    const int g = lane >> 3, l7 = lane & 7;
    for (int kt = 0; kt < NK; kt++) {
        const int buf = kt & 1;
        if (kt + 1 < NK) { LOADT(kt + 1, buf ^ 1); CP_COMMIT(); CP_WAIT1(); }
        else             { CP_WAIT0(); }
        __syncthreads();

        const uint32_t sA  = sbase + buf * 4 * TILEB;
        const uint32_t sAl = sA + TILEB;
        const uint32_t sB  = sA + 2 * TILEB;
        const uint32_t sBl = sA + 3 * TILEB;

        #pragma unroll
        for (int ks = 0; ks < 2; ks++) {
            uint32_t bh[4][2], bl[4][2];
            #pragma unroll
            for (int nj = 0; nj < 2; nj++) {
                uint32_t nrow = wn * 32 + nj * 16 + (g >> 1) * 8 + l7;
                uint32_t kb = ks * 32 + (g & 1) * 16;
                uint32_t r[4];
                ldsm4(r, sB + nrow * BPITCH + kb);
                bh[nj * 2 + 0][0] = r[0]; bh[nj * 2 + 0][1] = r[1];
                bh[nj * 2 + 1][0] = r[2]; bh[nj * 2 + 1][1] = r[3];
                ldsm4(r, sBl + nrow * BPITCH + kb);
                bl[nj * 2 + 0][0] = r[0]; bl[nj * 2 + 0][1] = r[1];
                bl[nj * 2 + 1][0] = r[2]; bl[nj * 2 + 1][1] = r[3];
            }
            #pragma unroll
            for (int mi = 0; mi < 4; mi++) {
                uint32_t arow = wm * 64 + mi * 16 + (g & 1) * 8 + l7;
                uint32_t kb = ks * 32 + (g >> 1) * 16;
                uint32_t ahf[4], alf[4];
                ldsm4(ahf, sA  + arow * BPITCH + kb);
                ldsm4(alf, sAl + arow * BPITCH + kb);
                #pragma unroll
                for (int ni = 0; ni < 4; ni++) {
                    mma_bf16(acc[mi][ni], ahf, bh[ni]);
                    mma_bf16(acc[mi][ni], ahf, bl[ni]);
                    mma_bf16(acc[mi][ni], alf, bh[ni]);
                }
            }
        }
        __syncthreads();
    }
    #undef LOADT

    #pragma unroll
    for (int mi = 0; mi < 4; mi++) {
        #pragma unroll
        for (int ni = 0; ni < 4; ni++) {
            int row = m0 + wm * 64 + mi * 16 + (lane >> 2);
            int col = n0 + wn * 32 + ni * 8 + 2 * (lane & 3);
            float b0 = 0.f, b1 = 0.f;
            if (bias) { b0 = bias[col]; b1 = bias[col + 1]; }
            #pragma unroll
            for (int h = 0; h < 2; h++) {
                float v0 = acc[mi][ni][2 * h + 0] + b0;
                float v1 = acc[mi][ni][2 * h + 1] + b1;
                if (ACT == 1) { v0 = fmaxf(v0, 0.f); v1 = fmaxf(v1, 0.f); }
                else if (ACT == 2) {
                    v0 = 1.0f / (1.0f + expf(-v0));
                    v1 = 1.0f / (1.0f + expf(-v1));
                }
                size_t o = (size_t)(row + 8 * h) * ldc + col;
                if (C)  *(float2*)&C[o] = make_float2(v0, v1);
                if (C2) { C2[o] = v0; C2[o + 1] = v1; }
                if (Ch) {
                    __nv_bfloat16 h0, l0, h1, l1;
                    split_bf16(v0, h0, l0);
                    split_bf16(v1, h1, l1);
                    *(__nv_bfloat162*)&Ch[o] = __nv_bfloat162(h0, h1);
                    *(__nv_bfloat162*)&Cl[o] = __nv_bfloat162(l0, l1);
                }
            }
        }
    }
}

// ================= conversions =================
__global__ __launch_bounds__(256) void conv_a_kernel(const float4* __restrict__ src,
                                                     __nv_bfloat162* __restrict__ h,
                                                     __nv_bfloat162* __restrict__ l,
                                                     size_t n4) {
    size_t stride = (size_t)gridDim.x * blockDim.x;
    for (size_t i = (size_t)blockIdx.x * blockDim.x + threadIdx.x; i < n4; i += stride) {
        float4 v = src[i];
        __nv_bfloat16 h0, l0, h1, l1, h2, l2, h3, l3;
        split_bf16(v.x, h0, l0); split_bf16(v.y, h1, l1);
        split_bf16(v.z, h2, l2); split_bf16(v.w, h3, l3);
        h[2 * i]     = __nv_bfloat162(h0, h1);
        h[2 * i + 1] = __nv_bfloat162(h2, h3);
        l[2 * i]     = __nv_bfloat162(l0, l1);
        l[2 * i + 1] = __nv_bfloat162(l2, l3);
    }
}
// transposed: src[R][C] fp32 -> dst[C][R] bf16 hi/lo
__global__ void conv_bt_kernel(const float* __restrict__ src,
                               __nv_bfloat16* __restrict__ h,
                               __nv_bfloat16* __restrict__ l, int R, int C) {
    __shared__ float t[32][33];
    int c = blockIdx.x * 32 + threadIdx.x;
    int r0 = blockIdx.y * 32;
    for (int dy = threadIdx.y; dy < 32; dy += 8)
        t[dy][threadIdx.x] = src[(size_t)(r0 + dy) * C + c];
    __syncthreads();
    int rr = r0 + threadIdx.x;
    int cc0 = blockIdx.x * 32;
    for (int dy = threadIdx.y; dy < 32; dy += 8) {
        float a = t[threadIdx.x][dy];
        __nv_bfloat16 bh, bl;
        split_bf16(a, bh, bl);
        size_t o = (size_t)(cc0 + dy) * R + rr;
        h[o] = bh;
        l[o] = bl;
    }
}

// ================= reductions =================
__device__ __forceinline__ float blk_reduce(float v, int op) {
    __shared__ float sh[32];
    __syncthreads();
    int lane = threadIdx.x & 31, wid = threadIdx.x >> 5;
    #pragma unroll
    for (int o = 16; o > 0; o >>= 1) {
        float w = __shfl_down_sync(0xffffffffu, v, o);
        v = op ? fmaxf(v, w) : v + w;
    }
    if (lane == 0) sh[wid] = v;
    __syncthreads();
    int nw = blockDim.x >> 5;
    v = (threadIdx.x < nw) ? sh[threadIdx.x] : (op ? -1e30f : 0.0f);
    if (wid == 0) {
        #pragma unroll
        for (int o = 16; o > 0; o >>= 1) {
            float w = __shfl_down_sync(0xffffffffu, v, o);
            v = op ? fmaxf(v, w) : v + w;
        }
        if (lane == 0) sh[0] = v;
    }
    __syncthreads();
    return sh[0];
}

// normalize: optional fp32 out, raw copy, bf16 hi/lo out, fused |dot| (loss_direct)
__global__ __launch_bounds__(256) void normalize_rows(const float* __restrict__ in,
                                                      float* __restrict__ out,
                                                      float* __restrict__ raw_copy,
                                                      __nv_bfloat16* __restrict__ oh,
                                                      __nv_bfloat16* __restrict__ ol,
                                                      const float* __restrict__ dotw) {
    int row = blockIdx.x;
    const float* x = in + (size_t)row * DD;
    float vv[4];
    float s = 0.0f, d = 0.0f;
    #pragma unroll
    for (int i = 0; i < 4; i++) {
        int k = threadIdx.x + i * 256;
        float v = x[k];
        vv[i] = v;
        s += v * v;
        if (dotw) d += v * dotw[(size_t)row * DD + k];
    }
    float tot = blk_reduce(s, 0);
    float inv = 1.0f / fmaxf(sqrtf(tot), EPSN);
    if (dotw) {
        float dt = blk_reduce(d, 0);
        if (threadIdx.x == 0) atomicAdd(&g_loss[2], (double)fabsf(dt * inv));
    }
    #pragma unroll
    for (int i = 0; i < 4; i++) {
        int k = threadIdx.x + i * 256;
        float v = vv[i] * inv;
        size_t o = (size_t)row * DD + k;
        if (out) out[o] = v;
        if (raw_copy) raw_copy[o] = vv[i];
        if (oh) {
            __nv_bfloat16 bh, bl;
            split_bf16(v, bh, bl);
            oh[o] = bh;
            ol[o] = bl;
        }
    }
}

__global__ void zero_kernel() {
    int i0 = blockIdx.x * blockDim.x + threadIdx.x;
    int stride = gridDim.x * blockDim.x;
    for (int i = i0; i < NCC * DD; i += stride) g_sums[i] = 0.0f;
    if (i0 < NCC) g_counts[i0] = 0.0f;
    if (i0 < 3) g_loss[i0] = 0.0;
}

__global__ __launch_bounds__(256) void argmax_kernel() {
    int row = blockIdx.x;
    const float* s = g_S + (size_t)row * NCC;
    int tid = threadIdx.x;
    __shared__ float sv[256];
    __shared__ int   si[256];
    {
        float best = -1e30f; int bidx = 0;
        for (int c = tid; c < NGC; c += 256) {
            float v = s[c];
            if (v > best) { best = v; bidx = c; }
        }
        sv[tid] = best; si[tid] = bidx;
        __syncthreads();
        for (int off = 128; off > 0; off >>= 1) {
            if (tid < off) {
                if (sv[tid + off] > sv[tid] ||
                    (sv[tid + off] == sv[tid] && si[tid + off] < si[tid])) {
                    sv[tid] = sv[tid + off]; si[tid] = si[tid + off];
                }
            }
            __syncthreads();
        }
        if (tid == 0) g_idx[row] = si[0];
        __syncthreads();
    }
    {
        float best = -1e30f; int bidx = 0;
        for (int c = tid; c < NLC; c += 256) {
            float v = s[NGC + c];
            if (v > best) { best = v; bidx = c; }
        }
        sv[tid] = best; si[tid] = bidx;
        __syncthreads();
        for (int off = 128; off > 0; off >>= 1) {
            if (tid < off) {
                if (sv[tid + off] > sv[tid] ||
                    (sv[tid + off] == sv[tid] && si[tid + off] < si[tid])) {
                    sv[tid] = sv[tid + off]; si[tid] = si[tid + off];
                }
            }
            __syncthreads();
        }
        if (tid == 0) g_idx[NROWS + row] = si[0];
    }
}

__global__ __launch_bounds__(256) void scatter_kernel(const float* __restrict__ unorm) {
    int row = blockIdx.x;
    int cg = g_idx[row];
    int cl = g_idx[NROWS + row] + NGC;
    const float* u = unorm + (size_t)row * DD;
    float* sg = g_sums + (size_t)cg * DD;
    float* sl = g_sums + (size_t)cl * DD;
    for (int k = threadIdx.x; k < DD; k += 256) {
        float v = u[k];
        atomicAdd(&sg[k], v);
        atomicAdd(&sl[k], v);
    }
    if (threadIdx.x == 0) {
        atomicAdd(&g_counts[cg], 1.0f);
        atomicAdd(&g_counts[cl], 1.0f);
    }
}

__global__ __launch_bounds__(256) void dict_update(const float* __restrict__ gdict,
                                                   const float* __restrict__ ldict) {
    int c = blockIdx.x;
    const float* d = (c < NGC) ? (gdict + (size_t)c * DD)
                               : (ldict + (size_t)(c - NGC) * DD);
    float m = (c < NGC) ? MOM_G : MOM_L;
    float cnt = g_counts[c];
    float invc = 1.0f / fmaxf(cnt, 1.0f);
    float vals[4];
    float s = 0.0f;
    #pragma unroll
    for (int i = 0; i < 4; i++) {
        int k = threadIdx.x + i * 256;
        float dv = d[k];
        float up = (cnt > 0.0f) ? (m * dv + (1.0f - m) * g_sums[(size_t)c * DD + k] * invc)
                                : dv;
        vals[i] = up;
        s += up * up;
    }
    float tot = blk_reduce(s, 0);
    float inv = 1.0f / fmaxf(sqrtf(tot), EPSN);
    #pragma unroll
    for (int i = 0; i < 4; i++) {
        int k = threadIdx.x + i * 256;
        g_comb[(size_t)c * DD + k] = vals[i] * inv;
    }
}

// fused: loss_g/loss_l |.| sums + row softmax -> bf16 hi/lo only
__global__ __launch_bounds__(256) void softmax_loss_kernel(__nv_bfloat16* __restrict__ oh,
                                                           __nv_bfloat16* __restrict__ ol) {
    int row = blockIdx.x;
    const float* s = g_S + (size_t)row * NCC;
    int tid = threadIdx.x;
    float lv[5];
    float m = -1e30f, sg = 0.0f, sl = 0.0f;
    #pragma unroll
    for (int i = 0; i < 5; i++) {
        int c = tid + i * 256;
        lv[i] = s[c];
        m = fmaxf(m, lv[i]);
        if (c < NGC) sg += fabsf(lv[i]); else sl += fabsf(lv[i]);
    }
    float bg = blk_reduce(sg, 0);
    if (tid == 0) atomicAdd(&g_loss[0], (double)bg);
    float bl = blk_reduce(sl, 0);
    if (tid == 0) atomicAdd(&g_loss[1], (double)bl);
    float M = blk_reduce(m, 1);
    float sum = 0.0f;
    #pragma unroll
    for (int i = 0; i < 5; i++) { lv[i] = expf((lv[i] - M) * TEMP_INV); sum += lv[i]; }
    float S = blk_reduce(sum, 0);
    float inv = 1.0f / S;
    #pragma unroll
    for (int i = 0; i < 5; i++) {
        float v = lv[i] * inv;
        __nv_bfloat16 bh, blo;
        split_bf16(v, bh, blo);
        size_t o = (size_t)row * NCC + tid + i * 256;
        oh[o] = bh;
        ol[o] = blo;
    }
}

__global__ __launch_bounds__(256) void final_kernel(const float* __restrict__ z,
                                                    const float* __restrict__ gate,
                                                    const float* __restrict__ wu,
                                                    float* __restrict__ out) {
    size_t stride = (size_t)gridDim.x * blockDim.x;
    for (size_t i = (size_t)blockIdx.x * blockDim.x + threadIdx.x;
         i < (size_t)NROWS * DD; i += stride)
        out[i] = z[i] - gate[i] * wu[i];
}

__global__ void write_loss(float* out_loss) {
    if (threadIdx.x == 0 && blockIdx.x == 0) {
        double l = g_loss[0] / ((double)NROWS * NGC)
                 + g_loss[1] / ((double)NROWS * NLC)
                 + g_loss[2] / (double)NROWS;
        out_loss[0] = (float)l;
    }
}

// ================= host launch =================
extern "C" void kernel_launch(void* const* d_in, const int* in_sizes, int n_in,
                              void* d_out, int out_size) {
    const float* z     = (const float*)d_in[0];
    const float* u     = (const float*)d_in[1];
    const float* W1    = (const float*)d_in[2];
    const float* b1    = (const float*)d_in[3];
    const float* W2    = (const float*)d_in[4];
    const float* b2    = (const float*)d_in[5];
    const float* Wg    = (const float*)d_in[6];
    const float* bg    = (const float*)d_in[7];
    const float* gdict = (const float*)d_in[8];
    const float* ldict = (const float*)d_in[9];

    float* out        = (float*)d_out;
    float* out_zclean = out;
    float* out_loss   = out + (size_t)NROWS * DD;
    float* out_zproj  = out_loss + 1;
    float* out_u      = out_zproj + (size_t)NROWS * DD;

    float *gate, *zproj, *unorm, *S, *comb;
    __nv_bfloat16 *P1h, *P1l, *P2h, *P2l, *P3h, *P3l, *P4h, *P4l, *Bh, *Bl;
    cudaGetSymbolAddress((void**)&gate,  g_gate);
    cudaGetSymbolAddress((void**)&zproj, g_zproj);
    cudaGetSymbolAddress((void**)&unorm, g_unorm);
    cudaGetSymbolAddress((void**)&S,     g_S);
    cudaGetSymbolAddress((void**)&comb,  g_comb);
    cudaGetSymbolAddress((void**)&P1h, g_P1h); cudaGetSymbolAddress((void**)&P1l, g_P1l);
    cudaGetSymbolAddress((void**)&P2h, g_P2h); cudaGetSymbolAddress((void**)&P2l, g_P2l);
    cudaGetSymbolAddress((void**)&P3h, g_P3h); cudaGetSymbolAddress((void**)&P3l, g_P3l);
    cudaGetSymbolAddress((void**)&P4h, g_P4h); cudaGetSymbolAddress((void**)&P4l, g_P4l);
    cudaGetSymbolAddress((void**)&Bh,  g_Bh);  cudaGetSymbolAddress((void**)&Bl,  g_Bl);
    float* wu = unorm;   // unorm fp32 dead after scatter + fused loss_direct

    const int SMEM_B = 8 * TILEB;   // 81920 B
    cudaFuncSetAttribute(bgemm<0>, cudaFuncAttributeMaxDynamicSharedMemorySize, SMEM_B);
    cudaFuncSetAttribute(bgemm<1>, cudaFuncAttributeMaxDynamicSharedMemorySize, SMEM_B);
    cudaFuncSetAttribute(bgemm<2>, cudaFuncAttributeMaxDynamicSharedMemorySize, SMEM_B);

    const dim3 TB(32, 8);
    const int MT = NROWS / 128;   // 256
    const size_t ND = (size_t)NROWS * DD;

    zero_kernel<<<1024, 256>>>();
    // u: fp32 unorm + raw copy + hi/lo for sim GEMM
    normalize_rows<<<NROWS, 256>>>(u, unorm, out_u, P3h, P3l, nullptr);

    // ---- projector ----
    conv_a_kernel<<<2048, 256>>>((const float4*)z, (__nv_bfloat162*)P1h,
                                 (__nv_bfloat162*)P1l, ND / 4);
    conv_bt_kernel<<<dim3(DD / 32, DD / 32), TB>>>(W1, Bh, Bl, DD, DD);
    bgemm<1><<<dim3(DD / 128, MT), 256, SMEM_B>>>(P1h, P1l, Bh, Bl, b1,
                                                  nullptr, nullptr, P2h, P2l, DD, DD, DD);
    conv_bt_kernel<<<dim3(DD / 32, DD / 32), TB>>>(W2, Bh, Bl, DD, DD);
    bgemm<0><<<dim3(DD / 128, MT), 256, SMEM_B>>>(P2h, P2l, Bh, Bl, b2,
                                                  zproj, out_zproj, P4h, P4l, DD, DD, DD);
    // znorm hi/lo (into P1, z dead) + fused loss_direct |dot(znorm, unorm)|
    normalize_rows<<<NROWS, 256>>>(zproj, nullptr, nullptr, P1h, P1l, unorm);

    // ---- sim vs OLD dicts (merged N=1280) ----
    conv_a_kernel<<<1024, 256>>>((const float4*)gdict, (__nv_bfloat162*)Bh,
                                 (__nv_bfloat162*)Bl, (size_t)NGC * DD / 4);
    conv_a_kernel<<<512, 256>>>((const float4*)ldict,
                                (__nv_bfloat162*)(Bh + (size_t)NGC * DD),
                                (__nv_bfloat162*)(Bl + (size_t)NGC * DD),
                                (size_t)NLC * DD / 4);
    bgemm<0><<<dim3(NCC / 128, MT), 256, SMEM_B>>>(P3h, P3l, Bh, Bl, nullptr,
                                                   S, nullptr, nullptr, nullptr,
                                                   NCC, DD, NCC);
    argmax_kernel<<<NROWS, 256>>>();
    scatter_kernel<<<NROWS, 256>>>(unorm);
    dict_update<<<NCC, 256>>>(gdict, ldict);

    // ---- logits vs UPDATED dicts -> fused losses+softmax(bf16) -> weighted_u ----
    conv_a_kernel<<<1024, 256>>>((const float4*)comb, (__nv_bfloat162*)Bh,
                                 (__nv_bfloat162*)Bl, (size_t)NCC * DD / 4);
    bgemm<0><<<dim3(NCC / 128, MT), 256, SMEM_B>>>(P1h, P1l, Bh, Bl, nullptr,
                                                   S, nullptr, nullptr, nullptr,
                                                   NCC, DD, NCC);
    softmax_loss_kernel<<<NROWS, 256>>>(P2h, P2l);
    conv_bt_kernel<<<dim3(DD / 32, NCC / 32), TB>>>(comb, Bh, Bl, NCC, DD);
    bgemm<0><<<dim3(DD / 128, MT), 256, SMEM_B>>>(P2h, P2l, Bh, Bl, nullptr,
                                                  wu, nullptr, nullptr, nullptr,
                                                  DD, NCC, DD);

    // ---- gate + final combine ----
    conv_bt_kernel<<<dim3(DD / 32, DD / 32), TB>>>(Wg, Bh, Bl, DD, DD);
    bgemm<2><<<dim3(DD / 128, MT), 256, SMEM_B>>>(P4h, P4l, Bh, Bl, bg,
                                                  gate, nullptr, nullptr, nullptr,
                                                  DD, DD, DD);
    final_kernel<<<2048, 256>>>(z, gate, wu, out_zclean);
    write_loss<<<1, 32>>>(out_loss);
}